// round 11
// baseline (speedup 1.0000x reference)
#include <cuda_runtime.h>
#include <cuda_bf16.h>
#include <math.h>
#include <stdint.h>

// ---------------- problem constants ----------------
#define Ln   2
#define Hn   2048
#define NHn  16
#define NKVn 2
#define HDn  128
#define Sn   1024
#define Pn   1024
#define FFn  5632
#define Tn   (Pn + Sn)       // 2048
#define Gn   (NHn / NKVn)    // 8
#define EPSn 1e-6f
#define SCALEn 0.08838834764831845f  // 1/sqrt(128)

typedef __nv_bfloat16 bf16;

// ---------------- device scratch (static, no allocation) ----------------
static __device__ float g_hid   [Sn * Hn];
static __device__ float g_qkv   [Sn * 2560];
static __device__ float g_bqkv  [2560];

static __device__ bf16 g_hn_hi[Sn * Hn],  g_hn_lo[Sn * Hn];
static __device__ bf16 g_q_hi [Sn * Hn],  g_q_lo [Sn * Hn];
static __device__ bf16 g_k_hi [NKVn * Tn * HDn], g_k_lo [NKVn * Tn * HDn];
static __device__ bf16 g_vt_hi[NKVn * HDn * Tn], g_vt_lo[NKVn * HDn * Tn];
static __device__ bf16 g_at_hi[Sn * Hn],  g_at_lo[Sn * Hn];
static __device__ bf16 g_g_hi [(size_t)Sn * FFn], g_g_lo [(size_t)Sn * FFn];

// transposed+split weights: per layer [wq(2048x2048), wk(256x2048), wv(256x2048),
//  wo(2048x2048), gu_interleaved(11264x2048), wd(2048x5632)]  (all [N,K])
#define WL 44040192LL
#define WTOT (2 * WL)
static __device__ bf16 g_w_hi[WTOT], g_w_lo[WTOT];

// ---------------- small helpers ----------------
__device__ __forceinline__ float warpSum(float v) {
#pragma unroll
    for (int o = 16; o; o >>= 1) v += __shfl_xor_sync(0xffffffffu, v, o);
    return v;
}
__device__ float blockSum256(float v) {
    __shared__ float sm[8]; __shared__ float res;
    v = warpSum(v);
    if ((threadIdx.x & 31) == 0) sm[threadIdx.x >> 5] = v;
    __syncthreads();
    float w = (threadIdx.x < 8) ? sm[threadIdx.x] : 0.f;
    w = warpSum(w);
    if (threadIdx.x == 0) res = w;
    __syncthreads();
    return res;
}

__device__ __forceinline__ void split_bf16(float x, bf16& h, bf16& l) {
    h = __float2bfloat16(x);
    l = __float2bfloat16(x - __bfloat162float(h));
}
__device__ __forceinline__ uint32_t b2u(__nv_bfloat162 v) {
    return *reinterpret_cast<uint32_t*>(&v);
}

// ---------------- PTX wrappers (plain sm_80+ features only) ----------------
__device__ __forceinline__ uint32_t smem_u32(const void* p) {
    uint32_t a;
    asm("{ .reg .u64 t; cvta.to.shared.u64 t, %1; cvt.u32.u64 %0, t; }" : "=r"(a) : "l"(p));
    return a;
}
__device__ __forceinline__ void cpa16(uint32_t d, const void* s) {
    asm volatile("cp.async.cg.shared.global [%0], [%1], 16;" :: "r"(d), "l"(s));
}
__device__ __forceinline__ void cp_commit() {
    asm volatile("cp.async.commit_group;" ::: "memory");
}
__device__ __forceinline__ void cp_wait2() {
    asm volatile("cp.async.wait_group 2;" ::: "memory");
}
__device__ __forceinline__ void cp_wait1() {
    asm volatile("cp.async.wait_group 1;" ::: "memory");
}
__device__ __forceinline__ void cp_wait0() {
    asm volatile("cp.async.wait_group 0;" ::: "memory");
}
__device__ __forceinline__ void ldm4(uint32_t* r, uint32_t a) {
    asm volatile("ldmatrix.sync.aligned.m8n8.x4.shared.b16 {%0,%1,%2,%3}, [%4];"
        : "=r"(r[0]), "=r"(r[1]), "=r"(r[2]), "=r"(r[3]) : "r"(a));
}
__device__ __forceinline__ void mma16816(float* c, const uint32_t* a, const uint32_t* b) {
    asm volatile(
        "mma.sync.aligned.m16n8k16.row.col.f32.bf16.bf16.f32 "
        "{%0,%1,%2,%3}, {%4,%5,%6,%7}, {%8,%9}, {%0,%1,%2,%3};"
        : "+f"(c[0]), "+f"(c[1]), "+f"(c[2]), "+f"(c[3])
        : "r"(a[0]), "r"(a[1]), "r"(a[2]), "r"(a[3]), "r"(b[0]), "r"(b[1]));
}

// ---------------- tensor-core GEMM (mma.sync bf16, 3-way split, 3-stage pipe) ----------------
// C[M,N] = A[M,K] @ B[N,K]^T. A/B are bf16 hi/lo pairs.
// MODE 0: fp32 out (+bias)(+Res).  MODE 1: gate/up interleaved cols -> silu(g)*u, bf16 hi/lo
//         out at [row, col/2] with row stride ldc.
#define AST  40                        // smem row stride in bf16 (80 B)
#define TILEB (128 * AST * 2)          // 10240 B per plane
#define STAGEB (4 * TILEB)             // Ah, Al, Bh, Bl
#define NSTAGE 3

template<int MODE>
__global__ void __launch_bounds__(256, 1)
mma_gemm(const bf16* __restrict__ Ah, const bf16* __restrict__ Al,
         const bf16* __restrict__ Bh, const bf16* __restrict__ Bl,
         const float* __restrict__ bias, const float* __restrict__ Res,
         float* __restrict__ Cf, bf16* __restrict__ Chi, bf16* __restrict__ Clo,
         int K, int lda, int ldb, int ldc)
{
    extern __shared__ char smc[];
    const int tid = threadIdx.x;
    const int lane = tid & 31;
    const int wid = tid >> 5;
    const int wm = wid >> 2;           // 0..1
    const int wn = wid & 3;            // 0..3
    const int row0 = blockIdx.y * 128;
    const int col0 = blockIdx.x * 128;

    const uint32_t smb = smem_u32(smc);

    float acc[4][4][4];
#pragma unroll
    for (int i = 0; i < 4; i++)
#pragma unroll
        for (int j = 0; j < 4; j++)
#pragma unroll
            for (int e = 0; e < 4; e++) acc[i][j][e] = 0.f;

    const int nk = K >> 5;

    auto load_tile = [&](int i) {
        const int k0 = i << 5;
        const uint32_t sb = smb + (i % NSTAGE) * STAGEB;
#pragma unroll
        for (int c = tid; c < 512; c += 256) {
            const int r = c >> 2, sg = c & 3;
            const uint32_t d = sb + r * (AST * 2) + sg * 16;
            const size_t ga = (size_t)(row0 + r) * lda + k0 + sg * 8;
            const size_t gb = (size_t)(col0 + r) * ldb + k0 + sg * 8;
            cpa16(d,             Ah + ga);
            cpa16(d + TILEB,     Al + ga);
            cpa16(d + 2 * TILEB, Bh + gb);
            cpa16(d + 3 * TILEB, Bl + gb);
        }
    };

    load_tile(0); cp_commit();
    load_tile(1); cp_commit();

    for (int i = 0; i < nk; i++) {
        if (i + 2 < nk) { load_tile(i + 2); cp_commit(); cp_wait2(); }
        else if (i + 1 < nk) cp_wait1();
        else cp_wait0();
        __syncthreads();

        const uint32_t sb = smb + (i % NSTAGE) * STAGEB;
#pragma unroll
        for (int ks = 0; ks < 2; ks++) {
            uint32_t ah[4][4], al[4][4], bh[4][2], bl[4][2];
            const int acol = ks * 32 + ((lane >> 4) & 1) * 16;
#pragma unroll
            for (int mt = 0; mt < 4; mt++) {
                const int row = wm * 64 + mt * 16 + ((lane >> 3) & 1) * 8 + (lane & 7);
                const uint32_t a = sb + row * (AST * 2) + acol;
                ldm4(ah[mt], a);
                ldm4(al[mt], a + TILEB);
            }
            const int bcol = ks * 32 + ((lane >> 3) & 1) * 16;
#pragma unroll
            for (int p = 0; p < 2; p++) {
                const int row = wn * 32 + p * 16 + ((lane >> 4) & 1) * 8 + (lane & 7);
                const uint32_t a = sb + 2 * TILEB + row * (AST * 2) + bcol;
                uint32_t r[4];
                ldm4(r, a);
                bh[2*p][0] = r[0]; bh[2*p][1] = r[1];
                bh[2*p+1][0] = r[2]; bh[2*p+1][1] = r[3];
                ldm4(r, a + TILEB);
                bl[2*p][0] = r[0]; bl[2*p][1] = r[1];
                bl[2*p+1][0] = r[2]; bl[2*p+1][1] = r[3];
            }
#pragma unroll
            for (int mt = 0; mt < 4; mt++)
#pragma unroll
                for (int nt = 0; nt < 4; nt++) {
                    mma16816(acc[mt][nt], ah[mt], bh[nt]);
                    mma16816(acc[mt][nt], ah[mt], bl[nt]);
                    mma16816(acc[mt][nt], al[mt], bh[nt]);
                }
        }
        __syncthreads();
    }

#pragma unroll
    for (int mt = 0; mt < 4; mt++) {
#pragma unroll
        for (int nt = 0; nt < 4; nt++) {
            const int row = row0 + wm * 64 + mt * 16 + (lane >> 2);
            const int col = col0 + wn * 32 + nt * 8 + (lane & 3) * 2;
            float v0 = acc[mt][nt][0];
            float v1 = acc[mt][nt][1];
            float v2 = acc[mt][nt][2];
            float v3 = acc[mt][nt][3];
            if (MODE == 0) {
                const long long o0 = (long long)row * ldc + col;
                const long long o1 = o0 + 8LL * ldc;
                if (bias) {
                    float b0 = __ldg(bias + col), b1 = __ldg(bias + col + 1);
                    v0 += b0; v1 += b1; v2 += b0; v3 += b1;
                }
                if (Res) {
                    float2 r0 = *reinterpret_cast<const float2*>(Res + o0);
                    float2 r1 = *reinterpret_cast<const float2*>(Res + o1);
                    v0 += r0.x; v1 += r0.y; v2 += r1.x; v3 += r1.y;
                }
                *reinterpret_cast<float2*>(Cf + o0) = make_float2(v0, v1);
                *reinterpret_cast<float2*>(Cf + o1) = make_float2(v2, v3);
            } else {
                // cols interleaved: even col = gate_j, odd = up_j, j = col/2
                const int j = col >> 1;
                const long long o0 = (long long)row * ldc + j;
                const long long o1 = o0 + 8LL * ldc;
                float r0 = v0 / (1.f + expf(-v0)) * v1;
                float r2 = v2 / (1.f + expf(-v2)) * v3;
                bf16 h, l;
                split_bf16(r0, h, l); Chi[o0] = h; Clo[o0] = l;
                split_bf16(r2, h, l); Chi[o1] = h; Clo[o1] = l;
            }
        }
    }
}

// ---------------- flash attention (fused QK^T -> softmax -> PV) ----------------
#define TkF   64
#define QSTRB 272                   // Q/K smem row stride bytes (136 bf16)
#define VSTRB 144                   // V smem row stride bytes (72 bf16)
#define QPL   (128 * QSTRB)
#define KPL   (64 * QSTRB)
#define VPL   (128 * VSTRB)
#define FSTG  (2 * KPL + 2 * VPL)
#define FKOFF (2 * QPL)
#define FSMEM (FKOFF + 2 * FSTG)    // 212992

__global__ void __launch_bounds__(256, 1)
flash_kernel(const bf16* __restrict__ qhp, const bf16* __restrict__ qlp,
             const bf16* __restrict__ khp, const bf16* __restrict__ klp,
             const bf16* __restrict__ vthp, const bf16* __restrict__ vtlp,
             bf16* __restrict__ ohp, bf16* __restrict__ olp)
{
    extern __shared__ char smc[];
    const uint32_t smb = smem_u32(smc);
    const int tid = threadIdx.x, lane = tid & 31, wid = tid >> 5;
    const int qb = blockIdx.x, h = blockIdx.y;
    const int row0 = qb * 128;
    const int kvh = h >> 3;
    const int nkt = 18 + 2 * qb;

    for (int c = tid; c < 2048; c += 256) {
        const int r = c >> 4, sg = c & 15;
        const uint32_t d = smb + r * QSTRB + sg * 16;
        const size_t src = (size_t)(row0 + r) * Hn + h * HDn + sg * 8;
        cpa16(d, qhp + src);
        cpa16(d + QPL, qlp + src);
    }
    cp_commit();

    auto load_kv = [&](int kt) {
        const int t0 = kt * TkF;
        const uint32_t base = smb + FKOFF + (kt & 1) * FSTG;
        for (int c = tid; c < 1024; c += 256) {
            const int r = c >> 4, sg = c & 15;
            const uint32_t d = base + r * QSTRB + sg * 16;
            const size_t src = ((size_t)kvh * Tn + t0 + r) * HDn + sg * 8;
            cpa16(d, khp + src);
            cpa16(d + KPL, klp + src);
        }
        for (int c = tid; c < 1024; c += 256) {
            const int r = c >> 3, sg = c & 7;
            const uint32_t d = base + 2 * KPL + r * VSTRB + sg * 16;
            const size_t src = ((size_t)kvh * HDn + r) * Tn + t0 + sg * 8;
            cpa16(d, vthp + src);
            cpa16(d + VPL, vtlp + src);
        }
    };
    load_kv(0); cp_commit();

    float O[16][4];
#pragma unroll
    for (int i = 0; i < 16; i++)
#pragma unroll
        for (int e = 0; e < 4; e++) O[i][e] = 0.f;
    float m1 = -1e30f, m2 = -1e30f, l1 = 0.f, l2 = 0.f;

    const int qrow1 = row0 + wid * 16 + (lane >> 2);
    const int lim1 = Pn + qrow1;
    const int lim2 = lim1 + 8;

    const uint32_t qbase = smb +
        (wid * 16 + ((lane >> 3) & 1) * 8 + (lane & 7)) * QSTRB + ((lane >> 4) & 1) * 16;
    const uint32_t brow = ((lane >> 4) & 1) * 8 + (lane & 7);
    const uint32_t bcol = ((lane >> 3) & 1) * 16;

    for (int kt = 0; kt < nkt; kt++) {
        if (kt + 1 < nkt) { load_kv(kt + 1); cp_commit(); cp_wait1(); }
        else cp_wait0();
        __syncthreads();
        const uint32_t base = smb + FKOFF + (kt & 1) * FSTG;

        float S[8][4];
#pragma unroll
        for (int nt = 0; nt < 8; nt++)
#pragma unroll
            for (int e = 0; e < 4; e++) S[nt][e] = 0.f;
#pragma unroll
        for (int ks = 0; ks < 8; ks++) {
            uint32_t qa_h[4], qa_l[4];
            ldm4(qa_h, qbase + ks * 32);
            ldm4(qa_l, qbase + ks * 32 + QPL);
#pragma unroll
            for (int p = 0; p < 4; p++) {
                uint32_t rh[4], rl[4];
                const uint32_t a = base + (p * 16 + brow) * QSTRB + ks * 32 + bcol;
                ldm4(rh, a);
                ldm4(rl, a + KPL);
                uint32_t bh0[2] = {rh[0], rh[1]}, bh1[2] = {rh[2], rh[3]};
                uint32_t bl0[2] = {rl[0], rl[1]}, bl1[2] = {rl[2], rl[3]};
                mma16816(S[2*p],   qa_h, bh0); mma16816(S[2*p],   qa_h, bl0); mma16816(S[2*p],   qa_l, bh0);
                mma16816(S[2*p+1], qa_h, bh1); mma16816(S[2*p+1], qa_h, bl1); mma16816(S[2*p+1], qa_l, bh1);
            }
        }

        const int t0 = kt * TkF;
        float mx1 = -1e30f, mx2 = -1e30f;
#pragma unroll
        for (int nt = 0; nt < 8; nt++) {
            const int tb = t0 + nt * 8 + (lane & 3) * 2;
#pragma unroll
            for (int e = 0; e < 2; e++) {
                S[nt][e]     = (tb + e <= lim1) ? S[nt][e]     * SCALEn : -1e30f;
                S[nt][2 + e] = (tb + e <= lim2) ? S[nt][2 + e] * SCALEn : -1e30f;
                mx1 = fmaxf(mx1, S[nt][e]);
                mx2 = fmaxf(mx2, S[nt][2 + e]);
            }
        }
        mx1 = fmaxf(mx1, __shfl_xor_sync(~0u, mx1, 1));
        mx1 = fmaxf(mx1, __shfl_xor_sync(~0u, mx1, 2));
        mx2 = fmaxf(mx2, __shfl_xor_sync(~0u, mx2, 1));
        mx2 = fmaxf(mx2, __shfl_xor_sync(~0u, mx2, 2));
        const float mn1 = fmaxf(m1, mx1), mn2 = fmaxf(m2, mx2);
        const float sc1 = __expf(fmaxf(m1 - mn1, -80.f));
        const float sc2 = __expf(fmaxf(m2 - mn2, -80.f));
        m1 = mn1; m2 = mn2;
        float rs1 = 0.f, rs2 = 0.f;
#pragma unroll
        for (int nt = 0; nt < 8; nt++) {
            S[nt][0] = __expf(fmaxf(S[nt][0] - mn1, -80.f));
            S[nt][1] = __expf(fmaxf(S[nt][1] - mn1, -80.f));
            S[nt][2] = __expf(fmaxf(S[nt][2] - mn2, -80.f));
            S[nt][3] = __expf(fmaxf(S[nt][3] - mn2, -80.f));
            rs1 += S[nt][0] + S[nt][1];
            rs2 += S[nt][2] + S[nt][3];
        }
        rs1 += __shfl_xor_sync(~0u, rs1, 1); rs1 += __shfl_xor_sync(~0u, rs1, 2);
        rs2 += __shfl_xor_sync(~0u, rs2, 1); rs2 += __shfl_xor_sync(~0u, rs2, 2);
        l1 = l1 * sc1 + rs1;
        l2 = l2 * sc2 + rs2;
#pragma unroll
        for (int i = 0; i < 16; i++) {
            O[i][0] *= sc1; O[i][1] *= sc1; O[i][2] *= sc2; O[i][3] *= sc2;
        }

#pragma unroll
        for (int ks2 = 0; ks2 < 4; ks2++) {
            uint32_t pa_h[4], pa_l[4];
#pragma unroll
            for (int half = 0; half < 2; half++) {
                const int nt = 2 * ks2 + half;
                bf16 h0, g0, h1, g1, h2, g2, h3, g3;
                split_bf16(S[nt][0], h0, g0); split_bf16(S[nt][1], h1, g1);
                split_bf16(S[nt][2], h2, g2); split_bf16(S[nt][3], h3, g3);
                pa_h[half ? 2 : 0] = b2u(__nv_bfloat162(h0, h1));
                pa_h[half ? 3 : 1] = b2u(__nv_bfloat162(h2, h3));
                pa_l[half ? 2 : 0] = b2u(__nv_bfloat162(g0, g1));
                pa_l[half ? 3 : 1] = b2u(__nv_bfloat162(g2, g3));
            }
#pragma unroll
            for (int p2 = 0; p2 < 8; p2++) {
                uint32_t rv[4], rvl[4];
                const uint32_t a = base + 2 * KPL + (p2 * 16 + brow) * VSTRB + ks2 * 32 + bcol;
                ldm4(rv, a);
                ldm4(rvl, a + VPL);
                uint32_t b0[2] = {rv[0], rv[1]},  b1[2] = {rv[2], rv[3]};
                uint32_t c0[2] = {rvl[0], rvl[1]}, c1[2] = {rvl[2], rvl[3]};
                mma16816(O[2*p2],   pa_h, b0); mma16816(O[2*p2],   pa_h, c0); mma16816(O[2*p2],   pa_l, b0);
                mma16816(O[2*p2+1], pa_h, b1); mma16816(O[2*p2+1], pa_h, c1); mma16816(O[2*p2+1], pa_l, b1);
            }
        }
        __syncthreads();
    }

    const float inv1 = 1.f / l1, inv2 = 1.f / l2;
    const int r1 = qrow1, r2 = qrow1 + 8;
    const int colb = h * HDn + (lane & 3) * 2;
#pragma unroll
    for (int nt2 = 0; nt2 < 16; nt2++) {
        const int col = colb + nt2 * 8;
        bf16 a0, b0, a1, b1;
        split_bf16(O[nt2][0] * inv1, a0, b0);
        split_bf16(O[nt2][1] * inv1, a1, b1);
        *reinterpret_cast<uint32_t*>(ohp + (size_t)r1 * Hn + col) = b2u(__nv_bfloat162(a0, a1));
        *reinterpret_cast<uint32_t*>(olp + (size_t)r1 * Hn + col) = b2u(__nv_bfloat162(b0, b1));
        split_bf16(O[nt2][2] * inv2, a0, b0);
        split_bf16(O[nt2][3] * inv2, a1, b1);
        *reinterpret_cast<uint32_t*>(ohp + (size_t)r2 * Hn + col) = b2u(__nv_bfloat162(a0, a1));
        *reinterpret_cast<uint32_t*>(olp + (size_t)r2 * Hn + col) = b2u(__nv_bfloat162(b0, b1));
    }
}

// ---------------- weight transpose + split: in[K,N] fp32 -> out[N*rmul+roff, K] bf16 hi/lo ----
// Tile 32 K-rows x 256 N-cols, 256 threads. 8 outstanding float4 loads/thread (MLP=8),
// 64 B contiguous stores per thread per plane.
struct __align__(16) B8 { bf16 v[8]; };

__global__ void __launch_bounds__(256)
convT_kernel(const float* __restrict__ in, bf16* __restrict__ hi, bf16* __restrict__ lo,
             int K, int N, int rmul, int roff)
{
    __shared__ float s[32][257];
    const int n0 = blockIdx.x * 256, k0 = blockIdx.y * 32;
    const int t = threadIdx.x;
    const int r = t >> 5, c8 = (t & 31) * 8;
    float4 v[4][2];
#pragma unroll
    for (int rr = 0; rr < 4; rr++) {
        const int k = r + rr * 8;
        const float* p = in + (size_t)(k0 + k) * N + n0 + c8;
        v[rr][0] = *reinterpret_cast<const float4*>(p);
        v[rr][1] = *reinterpret_cast<const float4*>(p + 4);
    }
#pragma unroll
    for (int rr = 0; rr < 4; rr++) {
        const int k = r + rr * 8;
        s[k][c8+0] = v[rr][0].x; s[k][c8+1] = v[rr][0].y;
        s[k][c8+2] = v[rr][0].z; s[k][c8+3] = v[rr][0].w;
        s[k][c8+4] = v[rr][1].x; s[k][c8+5] = v[rr][1].y;
        s[k][c8+6] = v[rr][1].z; s[k][c8+7] = v[rr][1].w;
    }
    __syncthreads();
    const int n = t;
    B8 hb[4], lb[4];
#pragma unroll
    for (int kk = 0; kk < 32; kk++) {
        bf16 h, l;
        split_bf16(s[kk][n], h, l);
        hb[kk >> 3].v[kk & 7] = h;
        lb[kk >> 3].v[kk & 7] = l;
    }
    const size_t o = (size_t)((n0 + n) * rmul + roff) * K + k0;
#pragma unroll
    for (int q = 0; q < 4; q++) {
        *reinterpret_cast<B8*>(hi + o + q * 8) = hb[q];
        *reinterpret_cast<B8*>(lo + o + q * 8) = lb[q];
    }
}

// ---------------- pack QKV biases into one 2560-vector ----------------
__global__ void packbias_kernel(const float* __restrict__ bq, const float* __restrict__ bk,
                                const float* __restrict__ bv, float* __restrict__ o)
{
    int i = blockIdx.x * 256 + threadIdx.x;
    if (i < 2048) o[i] = bq[i];
    else if (i < 2304) o[i] = bk[i - 2048];
    else if (i < 2560) o[i] = bv[i - 2304];
}

// ---------------- RMSNorm: MODE 0 -> fp32 out, MODE 1 -> bf16 hi/lo ----------------
template<int MODE>
__global__ void __launch_bounds__(256)
rmsnorm_kernel(const float* __restrict__ x, const float* __restrict__ w,
               float* __restrict__ yf, bf16* __restrict__ yh, bf16* __restrict__ yl)
{
    int s = blockIdx.x;
    const float* row = x + (size_t)s * Hn;
    float4 buf[2];
    float ss = 0.f;
#pragma unroll
    for (int it = 0; it < 2; it++) {
        int j = (it * 256 + threadIdx.x) * 4;
        float4 v = *reinterpret_cast<const float4*>(row + j);
        buf[it] = v;
        ss += v.x * v.x + v.y * v.y + v.z * v.z + v.w * v.w;
    }
    ss = blockSum256(ss);
    float inv = rsqrtf(ss * (1.0f / Hn) + EPSn);
#pragma unroll
    for (int it = 0; it < 2; it++) {
        int j = (it * 256 + threadIdx.x) * 4;
        float4 wv = *reinterpret_cast<const float4*>(w + j);
        float o0 = buf[it].x * inv * wv.x;
        float o1 = buf[it].y * inv * wv.y;
        float o2 = buf[it].z * inv * wv.z;
        float o3 = buf[it].w * inv * wv.w;
        if (MODE == 0) {
            *reinterpret_cast<float4*>(yf + (size_t)s * Hn + j) = make_float4(o0, o1, o2, o3);
        } else {
            bf16 h0,l0,h1,l1,h2,l2,h3,l3;
            split_bf16(o0,h0,l0); split_bf16(o1,h1,l1);
            split_bf16(o2,h2,l2); split_bf16(o3,h3,l3);
            __nv_bfloat162 hh0(h0,h1), hh1(h2,h3), ll0(l0,l1), ll1(l2,l3);
            uint2 uh = make_uint2(b2u(hh0), b2u(hh1));
            uint2 ul = make_uint2(b2u(ll0), b2u(ll1));
            *reinterpret_cast<uint2*>(yh + (size_t)s * Hn + j) = uh;
            *reinterpret_cast<uint2*>(yl + (size_t)s * Hn + j) = ul;
        }
    }
}

// ---------------- RoPE for Q: fp32 (strided in qkv) -> bf16 hi/lo dense [S,2048] ----------------
__global__ void rope_q_kernel(const float* __restrict__ qkv, const int* __restrict__ pos,
                              bf16* __restrict__ qh, bf16* __restrict__ ql)
{
    int s = blockIdx.x, h = blockIdx.y, d = threadIdx.x; // d in [0,64)
    double ang = (double)pos[s] * exp(-(double)d / 64.0 * 13.815510557964274);
    double sd, cd; sincos(ang, &sd, &cd);
    float c = (float)cd, sn = (float)sd;
    size_t ibase = (size_t)s * 2560 + h * HDn;
    size_t obase = ((size_t)s * NHn + h) * HDn;
    float x1 = qkv[ibase + d], x2 = qkv[ibase + d + 64];
    float v1 = x1 * c - x2 * sn;
    float v2 = x2 * c + x1 * sn;
    bf16 hh, ll;
    split_bf16(v1, hh, ll); qh[obase + d] = hh;      ql[obase + d] = ll;
    split_bf16(v2, hh, ll); qh[obase + d + 64] = hh; ql[obase + d + 64] = ll;
}

// ---------------- K/V cache: fp32 caches (to d_out) + bf16 hi/lo K + transposed V ----------------
__global__ void kv_cache_kernel(const float* __restrict__ qkv,
                                const float* __restrict__ pastk, const float* __restrict__ pastv,
                                const int* __restrict__ pos,
                                float* __restrict__ kc, float* __restrict__ vc,
                                bf16* __restrict__ kh, bf16* __restrict__ kl,
                                bf16* __restrict__ vth, bf16* __restrict__ vtl)
{
    int t = blockIdx.x, kv = blockIdx.y, d = threadIdx.x; // d in [0,128)
    size_t oidx = ((size_t)kv * Tn + t) * HDn + d;
    float kval, vval;
    if (t < Pn) {
        size_t pidx = ((size_t)kv * Pn + t) * HDn + d;
        kval = pastk[pidx];
        vval = pastv[pidx];
    } else {
        int s = t - Pn;
        const float* kr = qkv + (size_t)s * 2560 + 2048 + kv * HDn;
        int dr = d & 63;
        double ang = (double)pos[s] * exp(-(double)dr / 64.0 * 13.815510557964274);
        double sd, cd; sincos(ang, &sd, &cd);
        float c = (float)cd, sn = (float)sd;
        if (d < 64) kval = kr[d] * c - kr[d + 64] * sn;
        else        kval = kr[d] * c + kr[d - 64] * sn;
        vval = qkv[(size_t)s * 2560 + 2304 + kv * HDn + d];
    }
    kc[oidx] = kval;
    vc[oidx] = vval;
    bf16 h, l;
    split_bf16(kval, h, l); kh[oidx] = h; kl[oidx] = l;
    split_bf16(vval, h, l);
    size_t tidx = ((size_t)kv * HDn + d) * Tn + t;
    vth[tidx] = h; vtl[tidx] = l;
}

// ---------------- host-side launch helpers ----------------
static void mmagemm(const bf16* Ah, const bf16* Al, const bf16* Bh, const bf16* Bl,
                    const float* bias, const float* Res, float* Cf,
                    int M, int N, int K, int lda, int ldb, int ldc)
{
    dim3 grid(N / 128, M / 128, 1);
    mma_gemm<0><<<grid, 256, NSTAGE * STAGEB>>>(Ah, Al, Bh, Bl, bias, Res, Cf,
                                                nullptr, nullptr, K, lda, ldb, ldc);
}
static void mmagemm_gu(const bf16* Ah, const bf16* Al, const bf16* Bh, const bf16* Bl,
                       bf16* Chi, bf16* Clo, int M, int N, int K, int lda, int ldb, int ldc)
{
    dim3 grid(N / 128, M / 128, 1);
    mma_gemm<1><<<grid, 256, NSTAGE * STAGEB>>>(Ah, Al, Bh, Bl, nullptr, nullptr, nullptr,
                                                Chi, Clo, K, lda, ldb, ldc);
}

extern "C" void kernel_launch(void* const* d_in, const int* in_sizes, int n_in,
                              void* d_out, int out_size)
{
    (void)in_sizes; (void)n_in; (void)out_size;
    const float* embeds = (const float*)d_in[0];
    const int*   pos    = (const int*)  d_in[1];
    const float* past_k = (const float*)d_in[2];
    const float* past_v = (const float*)d_in[3];
    const float* ln1    = (const float*)d_in[4];
    const float* wq     = (const float*)d_in[5];
    const float* bq     = (const float*)d_in[6];
    const float* wk     = (const float*)d_in[7];
    const float* bk     = (const float*)d_in[8];
    const float* wv     = (const float*)d_in[9];
    const float* bv     = (const float*)d_in[10];
    const float* wo     = (const float*)d_in[11];
    const float* ln2    = (const float*)d_in[12];
    const float* wg     = (const float*)d_in[13];
    const float* wu     = (const float*)d_in[14];
    const float* wd     = (const float*)d_in[15];
    const float* normw  = (const float*)d_in[16];
    float* out = (float*)d_out;

    cudaFuncSetAttribute(mma_gemm<0>, cudaFuncAttributeMaxDynamicSharedMemorySize, NSTAGE * STAGEB);
    cudaFuncSetAttribute(mma_gemm<1>, cudaFuncAttributeMaxDynamicSharedMemorySize, NSTAGE * STAGEB);
    cudaFuncSetAttribute(flash_kernel, cudaFuncAttributeMaxDynamicSharedMemorySize, FSMEM);

    float *hid, *qkv, *bqkv;
    cudaGetSymbolAddress((void**)&hid,  g_hid);
    cudaGetSymbolAddress((void**)&qkv,  g_qkv);
    cudaGetSymbolAddress((void**)&bqkv, g_bqkv);
    bf16 *hnh,*hnl,*qh,*ql,*kh,*kl,*vth,*vtl,*ath,*atl,*gh,*gl,*wh,*wl;
    cudaGetSymbolAddress((void**)&hnh, g_hn_hi); cudaGetSymbolAddress((void**)&hnl, g_hn_lo);
    cudaGetSymbolAddress((void**)&qh,  g_q_hi);  cudaGetSymbolAddress((void**)&ql,  g_q_lo);
    cudaGetSymbolAddress((void**)&kh,  g_k_hi);  cudaGetSymbolAddress((void**)&kl,  g_k_lo);
    cudaGetSymbolAddress((void**)&vth, g_vt_hi); cudaGetSymbolAddress((void**)&vtl, g_vt_lo);
    cudaGetSymbolAddress((void**)&ath, g_at_hi); cudaGetSymbolAddress((void**)&atl, g_at_lo);
    cudaGetSymbolAddress((void**)&gh,  g_g_hi);  cudaGetSymbolAddress((void**)&gl,  g_g_lo);
    cudaGetSymbolAddress((void**)&wh,  g_w_hi);  cudaGetSymbolAddress((void**)&wl,  g_w_lo);

    // per-layer offsets into transposed weight store
    // [OQ: qkv 2560 rows][OO: wo 2048 rows][OG: gate/up interleaved 11264 rows][OD: wd 2048 rows]
    const long long OQ = 0, OO = 5242880, OG = 9437184, OD = 32505856;
    const long long OK_ = 4194304, OV = 4718592;

    // ---- transpose + split all weights ----
    dim3 cb(256);
    for (int l = 0; l < Ln; l++) {
        long long base = (long long)l * WL;
        convT_kernel<<<dim3(2048/256, 2048/32), cb>>>(wq + (size_t)l*Hn*2048, wh + base + OQ,  wl + base + OQ,  Hn, 2048, 1, 0);
        convT_kernel<<<dim3(256/256,  2048/32), cb>>>(wk + (size_t)l*Hn*256,  wh + base + OK_, wl + base + OK_, Hn, 256, 1, 0);
        convT_kernel<<<dim3(256/256,  2048/32), cb>>>(wv + (size_t)l*Hn*256,  wh + base + OV,  wl + base + OV,  Hn, 256, 1, 0);
        convT_kernel<<<dim3(2048/256, 2048/32), cb>>>(wo + (size_t)l*Hn*Hn,   wh + base + OO,  wl + base + OO,  Hn, 2048, 1, 0);
        convT_kernel<<<dim3(5632/256, 2048/32), cb>>>(wg + (size_t)l*Hn*FFn,  wh + base + OG,  wl + base + OG,  Hn, FFn, 2, 0);
        convT_kernel<<<dim3(5632/256, 2048/32), cb>>>(wu + (size_t)l*Hn*FFn,  wh + base + OG,  wl + base + OG,  Hn, FFn, 2, 1);
        convT_kernel<<<dim3(2048/256, 5632/32), cb>>>(wd + (size_t)l*FFn*Hn,  wh + base + OD,  wl + base + OD,  FFn, 2048, 1, 0);
    }

    cudaMemcpyAsync(hid, embeds, sizeof(float) * Sn * Hn, cudaMemcpyDeviceToDevice);

    for (int l = 0; l < Ln; l++) {
        long long base = (long long)l * WL;
        float* kc = out + (size_t)Sn * Hn + (size_t)l * 2 * NKVn * Tn * HDn;
        float* vc = kc + (size_t)NKVn * Tn * HDn;

        // pre-attention norm -> bf16 hi/lo
        rmsnorm_kernel<1><<<Sn, 256>>>(hid, ln1 + (size_t)l * Hn, nullptr, hnh, hnl);

        // fused QKV projection (N=2560) -> fp32 qkv buffer
        packbias_kernel<<<10, 256>>>(bq + (size_t)l*2048, bk + (size_t)l*256, bv + (size_t)l*256, bqkv);
        mmagemm(hnh, hnl, wh + base + OQ, wl + base + OQ, bqkv, nullptr,
                qkv, Sn, 2560, Hn, Hn, Hn, 2560);

        // RoPE Q -> bf16 hi/lo; KV cache (fp32 to d_out + bf16 hi/lo, V transposed)
        rope_q_kernel<<<dim3(Sn, NHn), 64>>>(qkv, pos, qh, ql);
        kv_cache_kernel<<<dim3(Tn, NKVn), HDn>>>(
            qkv,
            past_k + (size_t)l * NKVn * Pn * HDn,
            past_v + (size_t)l * NKVn * Pn * HDn,
            pos, kc, vc, kh, kl, vth, vtl);

        // fused attention: QK^T -> online softmax -> PV, bf16 hi/lo out
        flash_kernel<<<dim3(Sn / 128, NHn), 256, FSMEM>>>(qh, ql, kh, kl, vth, vtl, ath, atl);

        // output projection + residual (fp32)
        mmagemm(ath, atl, wh + base + OO, wl + base + OO, nullptr, hid,
                hid, Sn, Hn, Hn, Hn, Hn, Hn);

        // MLP: gate|up interleaved GEMM with fused SiLU epilogue -> bf16 hi/lo, then down
        rmsnorm_kernel<1><<<Sn, 256>>>(hid, ln2 + (size_t)l * Hn, nullptr, hnh, hnl);
        mmagemm_gu(hnh, hnl, wh + base + OG, wl + base + OG, gh, gl,
                   Sn, 2*FFn, Hn, Hn, Hn, FFn);
        mmagemm(gh, gl, wh + base + OD, wl + base + OD, nullptr, hid,
                hid, Sn, Hn, FFn, FFn, FFn, Hn);
    }

    // final norm -> fp32 hidden output
    rmsnorm_kernel<0><<<Sn, 256>>>(hid, normw, out, nullptr, nullptr);
}

// round 12
// speedup vs baseline: 1.0505x; 1.0505x over previous
#include <cuda_runtime.h>
#include <cuda_bf16.h>
#include <math.h>
#include <stdint.h>

// ---------------- problem constants ----------------
#define Ln   2
#define Hn   2048
#define NHn  16
#define NKVn 2
#define HDn  128
#define Sn   1024
#define Pn   1024
#define FFn  5632
#define Tn   (Pn + Sn)       // 2048
#define Gn   (NHn / NKVn)    // 8
#define EPSn 1e-6f
#define SCALEn 0.08838834764831845f  // 1/sqrt(128)

typedef __nv_bfloat16 bf16;

// ---------------- device scratch (static, no allocation) ----------------
static __device__ float g_hid   [Sn * Hn];
static __device__ float g_qkv   [Sn * 2560];
static __device__ float g_bqkv  [2560];

static __device__ bf16 g_hn_hi[Sn * Hn],  g_hn_lo[Sn * Hn];
static __device__ bf16 g_q_hi [Sn * Hn],  g_q_lo [Sn * Hn];
static __device__ bf16 g_k_hi [NKVn * Tn * HDn], g_k_lo [NKVn * Tn * HDn];
static __device__ bf16 g_vt_hi[NKVn * HDn * Tn], g_vt_lo[NKVn * HDn * Tn];
static __device__ bf16 g_at_hi[Sn * Hn],  g_at_lo[Sn * Hn];
static __device__ bf16 g_g_hi [(size_t)Sn * FFn], g_g_lo [(size_t)Sn * FFn];

// transposed+split weights: per layer [wq(2048x2048), wk(256x2048), wv(256x2048),
//  wo(2048x2048), gu_interleaved(11264x2048), wd(2048x5632)]  (all [N,K])
#define WL 44040192LL
#define WTOT (2 * WL)
static __device__ bf16 g_w_hi[WTOT], g_w_lo[WTOT];

// ---------------- small helpers ----------------
__device__ __forceinline__ float warpSum(float v) {
#pragma unroll
    for (int o = 16; o; o >>= 1) v += __shfl_xor_sync(0xffffffffu, v, o);
    return v;
}
__device__ float blockSum256(float v) {
    __shared__ float sm[8]; __shared__ float res;
    v = warpSum(v);
    if ((threadIdx.x & 31) == 0) sm[threadIdx.x >> 5] = v;
    __syncthreads();
    float w = (threadIdx.x < 8) ? sm[threadIdx.x] : 0.f;
    w = warpSum(w);
    if (threadIdx.x == 0) res = w;
    __syncthreads();
    return res;
}

__device__ __forceinline__ void split_bf16(float x, bf16& h, bf16& l) {
    h = __float2bfloat16(x);
    l = __float2bfloat16(x - __bfloat162float(h));
}
__device__ __forceinline__ uint32_t b2u(__nv_bfloat162 v) {
    return *reinterpret_cast<uint32_t*>(&v);
}

// ---------------- PTX wrappers (plain sm_80+ features only) ----------------
__device__ __forceinline__ uint32_t smem_u32(const void* p) {
    uint32_t a;
    asm("{ .reg .u64 t; cvta.to.shared.u64 t, %1; cvt.u32.u64 %0, t; }" : "=r"(a) : "l"(p));
    return a;
}
__device__ __forceinline__ void cpa16(uint32_t d, const void* s) {
    asm volatile("cp.async.cg.shared.global [%0], [%1], 16;" :: "r"(d), "l"(s));
}
__device__ __forceinline__ void cp_commit() {
    asm volatile("cp.async.commit_group;" ::: "memory");
}
__device__ __forceinline__ void cp_wait2() {
    asm volatile("cp.async.wait_group 2;" ::: "memory");
}
__device__ __forceinline__ void cp_wait1() {
    asm volatile("cp.async.wait_group 1;" ::: "memory");
}
__device__ __forceinline__ void cp_wait0() {
    asm volatile("cp.async.wait_group 0;" ::: "memory");
}
__device__ __forceinline__ void ldm4(uint32_t* r, uint32_t a) {
    asm volatile("ldmatrix.sync.aligned.m8n8.x4.shared.b16 {%0,%1,%2,%3}, [%4];"
        : "=r"(r[0]), "=r"(r[1]), "=r"(r[2]), "=r"(r[3]) : "r"(a));
}
__device__ __forceinline__ void mma16816(float* c, const uint32_t* a, const uint32_t* b) {
    asm volatile(
        "mma.sync.aligned.m16n8k16.row.col.f32.bf16.bf16.f32 "
        "{%0,%1,%2,%3}, {%4,%5,%6,%7}, {%8,%9}, {%0,%1,%2,%3};"
        : "+f"(c[0]), "+f"(c[1]), "+f"(c[2]), "+f"(c[3])
        : "r"(a[0]), "r"(a[1]), "r"(a[2]), "r"(a[3]), "r"(b[0]), "r"(b[1]));
}

// ---------------- tensor-core GEMM (mma.sync bf16, 3-way split, 3-stage pipe) ----------------
// C[M,N] = A[M,K] @ B[N,K]^T. A/B are bf16 hi/lo pairs.
// MODE 0: fp32 out (+bias)(+Res).  MODE 1: gate/up interleaved cols -> silu(g)*u, bf16 hi/lo
//         out at [row, col/2] with row stride ldc.
#define AST  40                        // smem row stride in bf16 (80 B)
#define TILEB (128 * AST * 2)          // 10240 B per plane
#define STAGEB (4 * TILEB)             // Ah, Al, Bh, Bl
#define NSTAGE 3

template<int MODE>
__global__ void __launch_bounds__(256, 1)
mma_gemm(const bf16* __restrict__ Ah, const bf16* __restrict__ Al,
         const bf16* __restrict__ Bh, const bf16* __restrict__ Bl,
         const float* __restrict__ bias, const float* __restrict__ Res,
         float* __restrict__ Cf, bf16* __restrict__ Chi, bf16* __restrict__ Clo,
         int K, int lda, int ldb, int ldc)
{
    extern __shared__ char smc[];
    const int tid = threadIdx.x;
    const int lane = tid & 31;
    const int wid = tid >> 5;
    const int wm = wid >> 2;           // 0..1
    const int wn = wid & 3;            // 0..3
    const int row0 = blockIdx.y * 128;
    const int col0 = blockIdx.x * 128;

    const uint32_t smb = smem_u32(smc);

    float acc[4][4][4];
#pragma unroll
    for (int i = 0; i < 4; i++)
#pragma unroll
        for (int j = 0; j < 4; j++)
#pragma unroll
            for (int e = 0; e < 4; e++) acc[i][j][e] = 0.f;

    const int nk = K >> 5;

    auto load_tile = [&](int i) {
        const int k0 = i << 5;
        const uint32_t sb = smb + (i % NSTAGE) * STAGEB;
#pragma unroll
        for (int c = tid; c < 512; c += 256) {
            const int r = c >> 2, sg = c & 3;
            const uint32_t d = sb + r * (AST * 2) + sg * 16;
            const size_t ga = (size_t)(row0 + r) * lda + k0 + sg * 8;
            const size_t gb = (size_t)(col0 + r) * ldb + k0 + sg * 8;
            cpa16(d,             Ah + ga);
            cpa16(d + TILEB,     Al + ga);
            cpa16(d + 2 * TILEB, Bh + gb);
            cpa16(d + 3 * TILEB, Bl + gb);
        }
    };

    load_tile(0); cp_commit();
    load_tile(1); cp_commit();

    for (int i = 0; i < nk; i++) {
        if (i + 2 < nk) { load_tile(i + 2); cp_commit(); cp_wait2(); }
        else if (i + 1 < nk) cp_wait1();
        else cp_wait0();
        __syncthreads();

        const uint32_t sb = smb + (i % NSTAGE) * STAGEB;
#pragma unroll
        for (int ks = 0; ks < 2; ks++) {
            uint32_t ah[4][4], al[4][4], bh[4][2], bl[4][2];
            const int acol = ks * 32 + ((lane >> 4) & 1) * 16;
#pragma unroll
            for (int mt = 0; mt < 4; mt++) {
                const int row = wm * 64 + mt * 16 + ((lane >> 3) & 1) * 8 + (lane & 7);
                const uint32_t a = sb + row * (AST * 2) + acol;
                ldm4(ah[mt], a);
                ldm4(al[mt], a + TILEB);
            }
            const int bcol = ks * 32 + ((lane >> 3) & 1) * 16;
#pragma unroll
            for (int p = 0; p < 2; p++) {
                const int row = wn * 32 + p * 16 + ((lane >> 4) & 1) * 8 + (lane & 7);
                const uint32_t a = sb + 2 * TILEB + row * (AST * 2) + bcol;
                uint32_t r[4];
                ldm4(r, a);
                bh[2*p][0] = r[0]; bh[2*p][1] = r[1];
                bh[2*p+1][0] = r[2]; bh[2*p+1][1] = r[3];
                ldm4(r, a + TILEB);
                bl[2*p][0] = r[0]; bl[2*p][1] = r[1];
                bl[2*p+1][0] = r[2]; bl[2*p+1][1] = r[3];
            }
#pragma unroll
            for (int mt = 0; mt < 4; mt++)
#pragma unroll
                for (int nt = 0; nt < 4; nt++) {
                    mma16816(acc[mt][nt], ah[mt], bh[nt]);
                    mma16816(acc[mt][nt], ah[mt], bl[nt]);
                    mma16816(acc[mt][nt], al[mt], bh[nt]);
                }
        }
        __syncthreads();
    }

#pragma unroll
    for (int mt = 0; mt < 4; mt++) {
#pragma unroll
        for (int nt = 0; nt < 4; nt++) {
            const int row = row0 + wm * 64 + mt * 16 + (lane >> 2);
            const int col = col0 + wn * 32 + nt * 8 + (lane & 3) * 2;
            float v0 = acc[mt][nt][0];
            float v1 = acc[mt][nt][1];
            float v2 = acc[mt][nt][2];
            float v3 = acc[mt][nt][3];
            if (MODE == 0) {
                const long long o0 = (long long)row * ldc + col;
                const long long o1 = o0 + 8LL * ldc;
                if (bias) {
                    float b0 = __ldg(bias + col), b1 = __ldg(bias + col + 1);
                    v0 += b0; v1 += b1; v2 += b0; v3 += b1;
                }
                if (Res) {
                    float2 r0 = *reinterpret_cast<const float2*>(Res + o0);
                    float2 r1 = *reinterpret_cast<const float2*>(Res + o1);
                    v0 += r0.x; v1 += r0.y; v2 += r1.x; v3 += r1.y;
                }
                *reinterpret_cast<float2*>(Cf + o0) = make_float2(v0, v1);
                *reinterpret_cast<float2*>(Cf + o1) = make_float2(v2, v3);
            } else {
                // cols interleaved: even col = gate_j, odd = up_j, j = col/2
                const int j = col >> 1;
                const long long o0 = (long long)row * ldc + j;
                const long long o1 = o0 + 8LL * ldc;
                float r0 = v0 / (1.f + expf(-v0)) * v1;
                float r2 = v2 / (1.f + expf(-v2)) * v3;
                bf16 h, l;
                split_bf16(r0, h, l); Chi[o0] = h; Clo[o0] = l;
                split_bf16(r2, h, l); Chi[o1] = h; Clo[o1] = l;
            }
        }
    }
}

// ---------------- flash attention (fused QK^T -> softmax -> PV) ----------------
#define TkF   64
#define QSTRB 272                   // Q/K smem row stride bytes (136 bf16)
#define VSTRB 144                   // V smem row stride bytes (72 bf16)
#define QPL   (128 * QSTRB)
#define KPL   (64 * QSTRB)
#define VPL   (128 * VSTRB)
#define FSTG  (2 * KPL + 2 * VPL)
#define FKOFF (2 * QPL)
#define FSMEM (FKOFF + 2 * FSTG)    // 212992

__global__ void __launch_bounds__(256, 1)
flash_kernel(const bf16* __restrict__ qhp, const bf16* __restrict__ qlp,
             const bf16* __restrict__ khp, const bf16* __restrict__ klp,
             const bf16* __restrict__ vthp, const bf16* __restrict__ vtlp,
             bf16* __restrict__ ohp, bf16* __restrict__ olp)
{
    extern __shared__ char smc[];
    const uint32_t smb = smem_u32(smc);
    const int tid = threadIdx.x, lane = tid & 31, wid = tid >> 5;
    const int qb = blockIdx.x, h = blockIdx.y;
    const int row0 = qb * 128;
    const int kvh = h >> 3;
    const int nkt = 18 + 2 * qb;

    for (int c = tid; c < 2048; c += 256) {
        const int r = c >> 4, sg = c & 15;
        const uint32_t d = smb + r * QSTRB + sg * 16;
        const size_t src = (size_t)(row0 + r) * Hn + h * HDn + sg * 8;
        cpa16(d, qhp + src);
        cpa16(d + QPL, qlp + src);
    }
    cp_commit();

    auto load_kv = [&](int kt) {
        const int t0 = kt * TkF;
        const uint32_t base = smb + FKOFF + (kt & 1) * FSTG;
        for (int c = tid; c < 1024; c += 256) {
            const int r = c >> 4, sg = c & 15;
            const uint32_t d = base + r * QSTRB + sg * 16;
            const size_t src = ((size_t)kvh * Tn + t0 + r) * HDn + sg * 8;
            cpa16(d, khp + src);
            cpa16(d + KPL, klp + src);
        }
        for (int c = tid; c < 1024; c += 256) {
            const int r = c >> 3, sg = c & 7;
            const uint32_t d = base + 2 * KPL + r * VSTRB + sg * 16;
            const size_t src = ((size_t)kvh * HDn + r) * Tn + t0 + sg * 8;
            cpa16(d, vthp + src);
            cpa16(d + VPL, vtlp + src);
        }
    };
    load_kv(0); cp_commit();

    float O[16][4];
#pragma unroll
    for (int i = 0; i < 16; i++)
#pragma unroll
        for (int e = 0; e < 4; e++) O[i][e] = 0.f;
    float m1 = -1e30f, m2 = -1e30f, l1 = 0.f, l2 = 0.f;

    const int qrow1 = row0 + wid * 16 + (lane >> 2);
    const int lim1 = Pn + qrow1;
    const int lim2 = lim1 + 8;

    const uint32_t qbase = smb +
        (wid * 16 + ((lane >> 3) & 1) * 8 + (lane & 7)) * QSTRB + ((lane >> 4) & 1) * 16;
    const uint32_t brow = ((lane >> 4) & 1) * 8 + (lane & 7);
    const uint32_t bcol = ((lane >> 3) & 1) * 16;

    for (int kt = 0; kt < nkt; kt++) {
        if (kt + 1 < nkt) { load_kv(kt + 1); cp_commit(); cp_wait1(); }
        else cp_wait0();
        __syncthreads();
        const uint32_t base = smb + FKOFF + (kt & 1) * FSTG;

        float S[8][4];
#pragma unroll
        for (int nt = 0; nt < 8; nt++)
#pragma unroll
            for (int e = 0; e < 4; e++) S[nt][e] = 0.f;
#pragma unroll
        for (int ks = 0; ks < 8; ks++) {
            uint32_t qa_h[4], qa_l[4];
            ldm4(qa_h, qbase + ks * 32);
            ldm4(qa_l, qbase + ks * 32 + QPL);
#pragma unroll
            for (int p = 0; p < 4; p++) {
                uint32_t rh[4], rl[4];
                const uint32_t a = base + (p * 16 + brow) * QSTRB + ks * 32 + bcol;
                ldm4(rh, a);
                ldm4(rl, a + KPL);
                uint32_t bh0[2] = {rh[0], rh[1]}, bh1[2] = {rh[2], rh[3]};
                uint32_t bl0[2] = {rl[0], rl[1]}, bl1[2] = {rl[2], rl[3]};
                mma16816(S[2*p],   qa_h, bh0); mma16816(S[2*p],   qa_h, bl0); mma16816(S[2*p],   qa_l, bh0);
                mma16816(S[2*p+1], qa_h, bh1); mma16816(S[2*p+1], qa_h, bl1); mma16816(S[2*p+1], qa_l, bh1);
            }
        }

        const int t0 = kt * TkF;
        float mx1 = -1e30f, mx2 = -1e30f;
#pragma unroll
        for (int nt = 0; nt < 8; nt++) {
            const int tb = t0 + nt * 8 + (lane & 3) * 2;
#pragma unroll
            for (int e = 0; e < 2; e++) {
                S[nt][e]     = (tb + e <= lim1) ? S[nt][e]     * SCALEn : -1e30f;
                S[nt][2 + e] = (tb + e <= lim2) ? S[nt][2 + e] * SCALEn : -1e30f;
                mx1 = fmaxf(mx1, S[nt][e]);
                mx2 = fmaxf(mx2, S[nt][2 + e]);
            }
        }
        mx1 = fmaxf(mx1, __shfl_xor_sync(~0u, mx1, 1));
        mx1 = fmaxf(mx1, __shfl_xor_sync(~0u, mx1, 2));
        mx2 = fmaxf(mx2, __shfl_xor_sync(~0u, mx2, 1));
        mx2 = fmaxf(mx2, __shfl_xor_sync(~0u, mx2, 2));
        const float mn1 = fmaxf(m1, mx1), mn2 = fmaxf(m2, mx2);
        const float sc1 = __expf(fmaxf(m1 - mn1, -80.f));
        const float sc2 = __expf(fmaxf(m2 - mn2, -80.f));
        m1 = mn1; m2 = mn2;
        float rs1 = 0.f, rs2 = 0.f;
#pragma unroll
        for (int nt = 0; nt < 8; nt++) {
            S[nt][0] = __expf(fmaxf(S[nt][0] - mn1, -80.f));
            S[nt][1] = __expf(fmaxf(S[nt][1] - mn1, -80.f));
            S[nt][2] = __expf(fmaxf(S[nt][2] - mn2, -80.f));
            S[nt][3] = __expf(fmaxf(S[nt][3] - mn2, -80.f));
            rs1 += S[nt][0] + S[nt][1];
            rs2 += S[nt][2] + S[nt][3];
        }
        rs1 += __shfl_xor_sync(~0u, rs1, 1); rs1 += __shfl_xor_sync(~0u, rs1, 2);
        rs2 += __shfl_xor_sync(~0u, rs2, 1); rs2 += __shfl_xor_sync(~0u, rs2, 2);
        l1 = l1 * sc1 + rs1;
        l2 = l2 * sc2 + rs2;
#pragma unroll
        for (int i = 0; i < 16; i++) {
            O[i][0] *= sc1; O[i][1] *= sc1; O[i][2] *= sc2; O[i][3] *= sc2;
        }

#pragma unroll
        for (int ks2 = 0; ks2 < 4; ks2++) {
            uint32_t pa_h[4], pa_l[4];
#pragma unroll
            for (int half = 0; half < 2; half++) {
                const int nt = 2 * ks2 + half;
                bf16 h0, g0, h1, g1, h2, g2, h3, g3;
                split_bf16(S[nt][0], h0, g0); split_bf16(S[nt][1], h1, g1);
                split_bf16(S[nt][2], h2, g2); split_bf16(S[nt][3], h3, g3);
                pa_h[half ? 2 : 0] = b2u(__nv_bfloat162(h0, h1));
                pa_h[half ? 3 : 1] = b2u(__nv_bfloat162(h2, h3));
                pa_l[half ? 2 : 0] = b2u(__nv_bfloat162(g0, g1));
                pa_l[half ? 3 : 1] = b2u(__nv_bfloat162(g2, g3));
            }
#pragma unroll
            for (int p2 = 0; p2 < 8; p2++) {
                uint32_t rv[4], rvl[4];
                const uint32_t a = base + 2 * KPL + (p2 * 16 + brow) * VSTRB + ks2 * 32 + bcol;
                ldm4(rv, a);
                ldm4(rvl, a + VPL);
                uint32_t b0[2] = {rv[0], rv[1]},  b1[2] = {rv[2], rv[3]};
                uint32_t c0[2] = {rvl[0], rvl[1]}, c1[2] = {rvl[2], rvl[3]};
                mma16816(O[2*p2],   pa_h, b0); mma16816(O[2*p2],   pa_h, c0); mma16816(O[2*p2],   pa_l, b0);
                mma16816(O[2*p2+1], pa_h, b1); mma16816(O[2*p2+1], pa_h, c1); mma16816(O[2*p2+1], pa_l, b1);
            }
        }
        __syncthreads();
    }

    const float inv1 = 1.f / l1, inv2 = 1.f / l2;
    const int r1 = qrow1, r2 = qrow1 + 8;
    const int colb = h * HDn + (lane & 3) * 2;
#pragma unroll
    for (int nt2 = 0; nt2 < 16; nt2++) {
        const int col = colb + nt2 * 8;
        bf16 a0, b0, a1, b1;
        split_bf16(O[nt2][0] * inv1, a0, b0);
        split_bf16(O[nt2][1] * inv1, a1, b1);
        *reinterpret_cast<uint32_t*>(ohp + (size_t)r1 * Hn + col) = b2u(__nv_bfloat162(a0, a1));
        *reinterpret_cast<uint32_t*>(olp + (size_t)r1 * Hn + col) = b2u(__nv_bfloat162(b0, b1));
        split_bf16(O[nt2][2] * inv2, a0, b0);
        split_bf16(O[nt2][3] * inv2, a1, b1);
        *reinterpret_cast<uint32_t*>(ohp + (size_t)r2 * Hn + col) = b2u(__nv_bfloat162(a0, a1));
        *reinterpret_cast<uint32_t*>(olp + (size_t)r2 * Hn + col) = b2u(__nv_bfloat162(b0, b1));
    }
}

// ---------------- weight transpose + split: in[K,N] fp32 -> out[N*rmul+roff, K] bf16 hi/lo ----
// Round-9 geometry (32x128 tile, 17KB smem, high occupancy) + register prefetch of loads.
struct __align__(16) B8 { bf16 v[8]; };

__global__ void __launch_bounds__(256)
convT_kernel(const float* __restrict__ in, bf16* __restrict__ hi, bf16* __restrict__ lo,
             int K, int N, int rmul, int roff)
{
    __shared__ float s[32][129];
    const int n0 = blockIdx.x * 128, k0 = blockIdx.y * 32;
    const int t = threadIdx.x;
    const int r = t >> 5, c4 = (t & 31) * 4;
    float4 v[4];
#pragma unroll
    for (int rr = 0; rr < 4; rr++)
        v[rr] = *reinterpret_cast<const float4*>(in + (size_t)(k0 + r + rr * 8) * N + n0 + c4);
#pragma unroll
    for (int rr = 0; rr < 4; rr++) {
        const int k = r + rr * 8;
        s[k][c4] = v[rr].x; s[k][c4+1] = v[rr].y; s[k][c4+2] = v[rr].z; s[k][c4+3] = v[rr].w;
    }
    __syncthreads();
    const int n = t >> 1, kk0 = (t & 1) * 16;
    B8 hb[2], lb[2];
#pragma unroll
    for (int kk = 0; kk < 16; kk++) {
        bf16 h, l;
        split_bf16(s[kk0 + kk][n], h, l);
        hb[kk >> 3].v[kk & 7] = h;
        lb[kk >> 3].v[kk & 7] = l;
    }
    const size_t o = (size_t)((n0 + n) * rmul + roff) * K + k0 + kk0;
    *reinterpret_cast<B8*>(hi + o)     = hb[0];
    *reinterpret_cast<B8*>(hi + o + 8) = hb[1];
    *reinterpret_cast<B8*>(lo + o)     = lb[0];
    *reinterpret_cast<B8*>(lo + o + 8) = lb[1];
}

// ---------------- pack QKV biases into one 2560-vector ----------------
__global__ void packbias_kernel(const float* __restrict__ bq, const float* __restrict__ bk,
                                const float* __restrict__ bv, float* __restrict__ o)
{
    int i = blockIdx.x * 256 + threadIdx.x;
    if (i < 2048) o[i] = bq[i];
    else if (i < 2304) o[i] = bk[i - 2048];
    else if (i < 2560) o[i] = bv[i - 2304];
}

// ---------------- RMSNorm: MODE 0 -> fp32 out, MODE 1 -> bf16 hi/lo ----------------
template<int MODE>
__global__ void __launch_bounds__(256)
rmsnorm_kernel(const float* __restrict__ x, const float* __restrict__ w,
               float* __restrict__ yf, bf16* __restrict__ yh, bf16* __restrict__ yl)
{
    int s = blockIdx.x;
    const float* row = x + (size_t)s * Hn;
    float4 buf[2];
    float ss = 0.f;
#pragma unroll
    for (int it = 0; it < 2; it++) {
        int j = (it * 256 + threadIdx.x) * 4;
        float4 v = *reinterpret_cast<const float4*>(row + j);
        buf[it] = v;
        ss += v.x * v.x + v.y * v.y + v.z * v.z + v.w * v.w;
    }
    ss = blockSum256(ss);
    float inv = rsqrtf(ss * (1.0f / Hn) + EPSn);
#pragma unroll
    for (int it = 0; it < 2; it++) {
        int j = (it * 256 + threadIdx.x) * 4;
        float4 wv = *reinterpret_cast<const float4*>(w + j);
        float o0 = buf[it].x * inv * wv.x;
        float o1 = buf[it].y * inv * wv.y;
        float o2 = buf[it].z * inv * wv.z;
        float o3 = buf[it].w * inv * wv.w;
        if (MODE == 0) {
            *reinterpret_cast<float4*>(yf + (size_t)s * Hn + j) = make_float4(o0, o1, o2, o3);
        } else {
            bf16 h0,l0,h1,l1,h2,l2,h3,l3;
            split_bf16(o0,h0,l0); split_bf16(o1,h1,l1);
            split_bf16(o2,h2,l2); split_bf16(o3,h3,l3);
            __nv_bfloat162 hh0(h0,h1), hh1(h2,h3), ll0(l0,l1), ll1(l2,l3);
            uint2 uh = make_uint2(b2u(hh0), b2u(hh1));
            uint2 ul = make_uint2(b2u(ll0), b2u(ll1));
            *reinterpret_cast<uint2*>(yh + (size_t)s * Hn + j) = uh;
            *reinterpret_cast<uint2*>(yl + (size_t)s * Hn + j) = ul;
        }
    }
}

// ---------------- RoPE for Q: fp32 (strided in qkv) -> bf16 hi/lo dense [S,2048] ----------------
__global__ void rope_q_kernel(const float* __restrict__ qkv, const int* __restrict__ pos,
                              bf16* __restrict__ qh, bf16* __restrict__ ql)
{
    int s = blockIdx.x, h = blockIdx.y, d = threadIdx.x; // d in [0,64)
    double ang = (double)pos[s] * exp(-(double)d / 64.0 * 13.815510557964274);
    double sd, cd; sincos(ang, &sd, &cd);
    float c = (float)cd, sn = (float)sd;
    size_t ibase = (size_t)s * 2560 + h * HDn;
    size_t obase = ((size_t)s * NHn + h) * HDn;
    float x1 = qkv[ibase + d], x2 = qkv[ibase + d + 64];
    float v1 = x1 * c - x2 * sn;
    float v2 = x2 * c + x1 * sn;
    bf16 hh, ll;
    split_bf16(v1, hh, ll); qh[obase + d] = hh;      ql[obase + d] = ll;
    split_bf16(v2, hh, ll); qh[obase + d + 64] = hh; ql[obase + d + 64] = ll;
}

// ---------------- K/V cache: fp32 caches (to d_out) + bf16 hi/lo K + transposed V ----------------
__global__ void kv_cache_kernel(const float* __restrict__ qkv,
                                const float* __restrict__ pastk, const float* __restrict__ pastv,
                                const int* __restrict__ pos,
                                float* __restrict__ kc, float* __restrict__ vc,
                                bf16* __restrict__ kh, bf16* __restrict__ kl,
                                bf16* __restrict__ vth, bf16* __restrict__ vtl)
{
    int t = blockIdx.x, kv = blockIdx.y, d = threadIdx.x; // d in [0,128)
    size_t oidx = ((size_t)kv * Tn + t) * HDn + d;
    float kval, vval;
    if (t < Pn) {
        size_t pidx = ((size_t)kv * Pn + t) * HDn + d;
        kval = pastk[pidx];
        vval = pastv[pidx];
    } else {
        int s = t - Pn;
        const float* kr = qkv + (size_t)s * 2560 + 2048 + kv * HDn;
        int dr = d & 63;
        double ang = (double)pos[s] * exp(-(double)dr / 64.0 * 13.815510557964274);
        double sd, cd; sincos(ang, &sd, &cd);
        float c = (float)cd, sn = (float)sd;
        if (d < 64) kval = kr[d] * c - kr[d + 64] * sn;
        else        kval = kr[d] * c + kr[d - 64] * sn;
        vval = qkv[(size_t)s * 2560 + 2304 + kv * HDn + d];
    }
    kc[oidx] = kval;
    vc[oidx] = vval;
    bf16 h, l;
    split_bf16(kval, h, l); kh[oidx] = h; kl[oidx] = l;
    split_bf16(vval, h, l);
    size_t tidx = ((size_t)kv * HDn + d) * Tn + t;
    vth[tidx] = h; vtl[tidx] = l;
}

// ---------------- host-side launch helpers ----------------
static void mmagemm(const bf16* Ah, const bf16* Al, const bf16* Bh, const bf16* Bl,
                    const float* bias, const float* Res, float* Cf,
                    int M, int N, int K, int lda, int ldb, int ldc)
{
    dim3 grid(N / 128, M / 128, 1);
    mma_gemm<0><<<grid, 256, NSTAGE * STAGEB>>>(Ah, Al, Bh, Bl, bias, Res, Cf,
                                                nullptr, nullptr, K, lda, ldb, ldc);
}
static void mmagemm_gu(const bf16* Ah, const bf16* Al, const bf16* Bh, const bf16* Bl,
                       bf16* Chi, bf16* Clo, int M, int N, int K, int lda, int ldb, int ldc)
{
    dim3 grid(N / 128, M / 128, 1);
    mma_gemm<1><<<grid, 256, NSTAGE * STAGEB>>>(Ah, Al, Bh, Bl, nullptr, nullptr, nullptr,
                                                Chi, Clo, K, lda, ldb, ldc);
}

extern "C" void kernel_launch(void* const* d_in, const int* in_sizes, int n_in,
                              void* d_out, int out_size)
{
    (void)in_sizes; (void)n_in; (void)out_size;
    const float* embeds = (const float*)d_in[0];
    const int*   pos    = (const int*)  d_in[1];
    const float* past_k = (const float*)d_in[2];
    const float* past_v = (const float*)d_in[3];
    const float* ln1    = (const float*)d_in[4];
    const float* wq     = (const float*)d_in[5];
    const float* bq     = (const float*)d_in[6];
    const float* wk     = (const float*)d_in[7];
    const float* bk     = (const float*)d_in[8];
    const float* wv     = (const float*)d_in[9];
    const float* bv     = (const float*)d_in[10];
    const float* wo     = (const float*)d_in[11];
    const float* ln2    = (const float*)d_in[12];
    const float* wg     = (const float*)d_in[13];
    const float* wu     = (const float*)d_in[14];
    const float* wd     = (const float*)d_in[15];
    const float* normw  = (const float*)d_in[16];
    float* out = (float*)d_out;

    cudaFuncSetAttribute(mma_gemm<0>, cudaFuncAttributeMaxDynamicSharedMemorySize, NSTAGE * STAGEB);
    cudaFuncSetAttribute(mma_gemm<1>, cudaFuncAttributeMaxDynamicSharedMemorySize, NSTAGE * STAGEB);
    cudaFuncSetAttribute(flash_kernel, cudaFuncAttributeMaxDynamicSharedMemorySize, FSMEM);

    float *hid, *qkv, *bqkv;
    cudaGetSymbolAddress((void**)&hid,  g_hid);
    cudaGetSymbolAddress((void**)&qkv,  g_qkv);
    cudaGetSymbolAddress((void**)&bqkv, g_bqkv);
    bf16 *hnh,*hnl,*qh,*ql,*kh,*kl,*vth,*vtl,*ath,*atl,*gh,*gl,*wh,*wl;
    cudaGetSymbolAddress((void**)&hnh, g_hn_hi); cudaGetSymbolAddress((void**)&hnl, g_hn_lo);
    cudaGetSymbolAddress((void**)&qh,  g_q_hi);  cudaGetSymbolAddress((void**)&ql,  g_q_lo);
    cudaGetSymbolAddress((void**)&kh,  g_k_hi);  cudaGetSymbolAddress((void**)&kl,  g_k_lo);
    cudaGetSymbolAddress((void**)&vth, g_vt_hi); cudaGetSymbolAddress((void**)&vtl, g_vt_lo);
    cudaGetSymbolAddress((void**)&ath, g_at_hi); cudaGetSymbolAddress((void**)&atl, g_at_lo);
    cudaGetSymbolAddress((void**)&gh,  g_g_hi);  cudaGetSymbolAddress((void**)&gl,  g_g_lo);
    cudaGetSymbolAddress((void**)&wh,  g_w_hi);  cudaGetSymbolAddress((void**)&wl,  g_w_lo);

    // per-layer offsets into transposed weight store
    // [OQ: qkv 2560 rows][OO: wo 2048 rows][OG: gate/up interleaved 11264 rows][OD: wd 2048 rows]
    const long long OQ = 0, OO = 5242880, OG = 9437184, OD = 32505856;
    const long long OK_ = 4194304, OV = 4718592;

    // ---- transpose + split all weights ----
    dim3 cb(256);
    for (int l = 0; l < Ln; l++) {
        long long base = (long long)l * WL;
        convT_kernel<<<dim3(2048/128, 2048/32), cb>>>(wq + (size_t)l*Hn*2048, wh + base + OQ,  wl + base + OQ,  Hn, 2048, 1, 0);
        convT_kernel<<<dim3(256/128,  2048/32), cb>>>(wk + (size_t)l*Hn*256,  wh + base + OK_, wl + base + OK_, Hn, 256, 1, 0);
        convT_kernel<<<dim3(256/128,  2048/32), cb>>>(wv + (size_t)l*Hn*256,  wh + base + OV,  wl + base + OV,  Hn, 256, 1, 0);
        convT_kernel<<<dim3(2048/128, 2048/32), cb>>>(wo + (size_t)l*Hn*Hn,   wh + base + OO,  wl + base + OO,  Hn, 2048, 1, 0);
        convT_kernel<<<dim3(5632/128, 2048/32), cb>>>(wg + (size_t)l*Hn*FFn,  wh + base + OG,  wl + base + OG,  Hn, FFn, 2, 0);
        convT_kernel<<<dim3(5632/128, 2048/32), cb>>>(wu + (size_t)l*Hn*FFn,  wh + base + OG,  wl + base + OG,  Hn, FFn, 2, 1);
        convT_kernel<<<dim3(2048/128, 5632/32), cb>>>(wd + (size_t)l*FFn*Hn,  wh + base + OD,  wl + base + OD,  FFn, 2048, 1, 0);
    }

    cudaMemcpyAsync(hid, embeds, sizeof(float) * Sn * Hn, cudaMemcpyDeviceToDevice);

    for (int l = 0; l < Ln; l++) {
        long long base = (long long)l * WL;
        float* kc = out + (size_t)Sn * Hn + (size_t)l * 2 * NKVn * Tn * HDn;
        float* vc = kc + (size_t)NKVn * Tn * HDn;

        // pre-attention norm -> bf16 hi/lo
        rmsnorm_kernel<1><<<Sn, 256>>>(hid, ln1 + (size_t)l * Hn, nullptr, hnh, hnl);

        // fused QKV projection (N=2560) -> fp32 qkv buffer
        packbias_kernel<<<10, 256>>>(bq + (size_t)l*2048, bk + (size_t)l*256, bv + (size_t)l*256, bqkv);
        mmagemm(hnh, hnl, wh + base + OQ, wl + base + OQ, bqkv, nullptr,
                qkv, Sn, 2560, Hn, Hn, Hn, 2560);

        // RoPE Q -> bf16 hi/lo; KV cache (fp32 to d_out + bf16 hi/lo, V transposed)
        rope_q_kernel<<<dim3(Sn, NHn), 64>>>(qkv, pos, qh, ql);
        kv_cache_kernel<<<dim3(Tn, NKVn), HDn>>>(
            qkv,
            past_k + (size_t)l * NKVn * Pn * HDn,
            past_v + (size_t)l * NKVn * Pn * HDn,
            pos, kc, vc, kh, kl, vth, vtl);

        // fused attention: QK^T -> online softmax -> PV, bf16 hi/lo out
        flash_kernel<<<dim3(Sn / 128, NHn), 256, FSMEM>>>(qh, ql, kh, kl, vth, vtl, ath, atl);

        // output projection + residual (fp32)
        mmagemm(ath, atl, wh + base + OO, wl + base + OO, nullptr, hid,
                hid, Sn, Hn, Hn, Hn, Hn, Hn);

        // MLP: gate|up interleaved GEMM with fused SiLU epilogue -> bf16 hi/lo, then down
        rmsnorm_kernel<1><<<Sn, 256>>>(hid, ln2 + (size_t)l * Hn, nullptr, hnh, hnl);
        mmagemm_gu(hnh, hnl, wh + base + OG, wl + base + OG, gh, gl,
                   Sn, 2*FFn, Hn, Hn, Hn, FFn);
        mmagemm(gh, gl, wh + base + OD, wl + base + OD, nullptr, hid,
                hid, Sn, Hn, FFn, FFn, FFn, Hn);
    }

    // final norm -> fp32 hidden output
    rmsnorm_kernel<0><<<Sn, 256>>>(hid, normw, out, nullptr, nullptr);
}

// round 14
// speedup vs baseline: 1.0717x; 1.0201x over previous
#include <cuda_runtime.h>
#include <cuda_bf16.h>
#include <math.h>
#include <stdint.h>

// ---------------- problem constants ----------------
#define Ln   2
#define Hn   2048
#define NHn  16
#define NKVn 2
#define HDn  128
#define Sn   1024
#define Pn   1024
#define FFn  5632
#define Tn   (Pn + Sn)       // 2048
#define Gn   (NHn / NKVn)    // 8
#define EPSn 1e-6f
#define SCALEn 0.08838834764831845f  // 1/sqrt(128)

typedef __nv_bfloat16 bf16;

// ---------------- device scratch (static, no allocation) ----------------
static __device__ float g_hid   [Sn * Hn];
static __device__ float g_qkv   [Sn * 2560];
static __device__ float g_bqkv  [2560];

static __device__ bf16 g_hn_hi[Sn * Hn],  g_hn_lo[Sn * Hn];
static __device__ bf16 g_q_hi [Sn * Hn],  g_q_lo [Sn * Hn];
static __device__ bf16 g_k_hi [NKVn * Tn * HDn], g_k_lo [NKVn * Tn * HDn];
static __device__ bf16 g_vt_hi[NKVn * HDn * Tn], g_vt_lo[NKVn * HDn * Tn];
static __device__ bf16 g_at_hi[Sn * Hn],  g_at_lo[Sn * Hn];
static __device__ bf16 g_g_hi [(size_t)Sn * FFn], g_g_lo [(size_t)Sn * FFn];

// transposed+split weights: per layer [wq(2048x2048), wk(256x2048), wv(256x2048),
//  wo(2048x2048), gu_interleaved(11264x2048), wd(2048x5632)]  (all [N,K])
#define WL 44040192LL
#define WTOT (2 * WL)
static __device__ bf16 g_w_hi[WTOT], g_w_lo[WTOT];

// ---------------- small helpers ----------------
__device__ __forceinline__ float warpSum(float v) {
#pragma unroll
    for (int o = 16; o; o >>= 1) v += __shfl_xor_sync(0xffffffffu, v, o);
    return v;
}
__device__ float blockSum256(float v) {
    __shared__ float sm[8]; __shared__ float res;
    v = warpSum(v);
    if ((threadIdx.x & 31) == 0) sm[threadIdx.x >> 5] = v;
    __syncthreads();
    float w = (threadIdx.x < 8) ? sm[threadIdx.x] : 0.f;
    w = warpSum(w);
    if (threadIdx.x == 0) res = w;
    __syncthreads();
    return res;
}

__device__ __forceinline__ void split_bf16(float x, bf16& h, bf16& l) {
    h = __float2bfloat16(x);
    l = __float2bfloat16(x - __bfloat162float(h));
}
__device__ __forceinline__ uint32_t b2u(__nv_bfloat162 v) {
    return *reinterpret_cast<uint32_t*>(&v);
}

// ---------------- PTX wrappers (plain sm_80+ features only) ----------------
__device__ __forceinline__ uint32_t smem_u32(const void* p) {
    uint32_t a;
    asm("{ .reg .u64 t; cvta.to.shared.u64 t, %1; cvt.u32.u64 %0, t; }" : "=r"(a) : "l"(p));
    return a;
}
__device__ __forceinline__ void cpa16(uint32_t d, const void* s) {
    asm volatile("cp.async.cg.shared.global [%0], [%1], 16;" :: "r"(d), "l"(s));
}
__device__ __forceinline__ void cp_commit() {
    asm volatile("cp.async.commit_group;" ::: "memory");
}
__device__ __forceinline__ void cp_wait2() {
    asm volatile("cp.async.wait_group 2;" ::: "memory");
}
__device__ __forceinline__ void cp_wait1() {
    asm volatile("cp.async.wait_group 1;" ::: "memory");
}
__device__ __forceinline__ void cp_wait0() {
    asm volatile("cp.async.wait_group 0;" ::: "memory");
}
__device__ __forceinline__ void ldm4(uint32_t* r, uint32_t a) {
    asm volatile("ldmatrix.sync.aligned.m8n8.x4.shared.b16 {%0,%1,%2,%3}, [%4];"
        : "=r"(r[0]), "=r"(r[1]), "=r"(r[2]), "=r"(r[3]) : "r"(a));
}
__device__ __forceinline__ void mma16816(float* c, const uint32_t* a, const uint32_t* b) {
    asm volatile(
        "mma.sync.aligned.m16n8k16.row.col.f32.bf16.bf16.f32 "
        "{%0,%1,%2,%3}, {%4,%5,%6,%7}, {%8,%9}, {%0,%1,%2,%3};"
        : "+f"(c[0]), "+f"(c[1]), "+f"(c[2]), "+f"(c[3])
        : "r"(a[0]), "r"(a[1]), "r"(a[2]), "r"(a[3]), "r"(b[0]), "r"(b[1]));
}

// ---------------- tensor-core GEMM (mma.sync bf16, 3-way split, 3-stage pipe) ----------------
// C[M,N] = A[M,K] @ B[N,K]^T. A/B are bf16 hi/lo pairs.
// MODE 0: fp32 out (+bias)(+Res).  MODE 1: gate/up interleaved cols -> silu(g)*u, bf16 hi/lo
//         out at [row, col/2] with row stride ldc.
#define AST  40                        // smem row stride in bf16 (80 B)
#define TILEB (128 * AST * 2)          // 10240 B per plane
#define STAGEB (4 * TILEB)             // Ah, Al, Bh, Bl
#define NSTAGE 3

template<int MODE>
__global__ void __launch_bounds__(256, 1)
mma_gemm(const bf16* __restrict__ Ah, const bf16* __restrict__ Al,
         const bf16* __restrict__ Bh, const bf16* __restrict__ Bl,
         const float* __restrict__ bias, const float* __restrict__ Res,
         float* __restrict__ Cf, bf16* __restrict__ Chi, bf16* __restrict__ Clo,
         int K, int lda, int ldb, int ldc)
{
    extern __shared__ char smc[];
    const int tid = threadIdx.x;
    const int lane = tid & 31;
    const int wid = tid >> 5;
    const int wm = wid >> 2;           // 0..1
    const int wn = wid & 3;            // 0..3
    const int row0 = blockIdx.y * 128;
    const int col0 = blockIdx.x * 128;

    const uint32_t smb = smem_u32(smc);

    float acc[4][4][4];
#pragma unroll
    for (int i = 0; i < 4; i++)
#pragma unroll
        for (int j = 0; j < 4; j++)
#pragma unroll
            for (int e = 0; e < 4; e++) acc[i][j][e] = 0.f;

    const int nk = K >> 5;

    auto load_tile = [&](int i) {
        const int k0 = i << 5;
        const uint32_t sb = smb + (i % NSTAGE) * STAGEB;
#pragma unroll
        for (int c = tid; c < 512; c += 256) {
            const int r = c >> 2, sg = c & 3;
            const uint32_t d = sb + r * (AST * 2) + sg * 16;
            const size_t ga = (size_t)(row0 + r) * lda + k0 + sg * 8;
            const size_t gb = (size_t)(col0 + r) * ldb + k0 + sg * 8;
            cpa16(d,             Ah + ga);
            cpa16(d + TILEB,     Al + ga);
            cpa16(d + 2 * TILEB, Bh + gb);
            cpa16(d + 3 * TILEB, Bl + gb);
        }
    };

    load_tile(0); cp_commit();
    load_tile(1); cp_commit();

    for (int i = 0; i < nk; i++) {
        if (i + 2 < nk) { load_tile(i + 2); cp_commit(); cp_wait2(); }
        else if (i + 1 < nk) cp_wait1();
        else cp_wait0();
        __syncthreads();

        const uint32_t sb = smb + (i % NSTAGE) * STAGEB;
#pragma unroll
        for (int ks = 0; ks < 2; ks++) {
            uint32_t ah[4][4], al[4][4], bh[4][2], bl[4][2];
            const int acol = ks * 32 + ((lane >> 4) & 1) * 16;
#pragma unroll
            for (int mt = 0; mt < 4; mt++) {
                const int row = wm * 64 + mt * 16 + ((lane >> 3) & 1) * 8 + (lane & 7);
                const uint32_t a = sb + row * (AST * 2) + acol;
                ldm4(ah[mt], a);
                ldm4(al[mt], a + TILEB);
            }
            const int bcol = ks * 32 + ((lane >> 3) & 1) * 16;
#pragma unroll
            for (int p = 0; p < 2; p++) {
                const int row = wn * 32 + p * 16 + ((lane >> 4) & 1) * 8 + (lane & 7);
                const uint32_t a = sb + 2 * TILEB + row * (AST * 2) + bcol;
                uint32_t r[4];
                ldm4(r, a);
                bh[2*p][0] = r[0]; bh[2*p][1] = r[1];
                bh[2*p+1][0] = r[2]; bh[2*p+1][1] = r[3];
                ldm4(r, a + TILEB);
                bl[2*p][0] = r[0]; bl[2*p][1] = r[1];
                bl[2*p+1][0] = r[2]; bl[2*p+1][1] = r[3];
            }
#pragma unroll
            for (int mt = 0; mt < 4; mt++)
#pragma unroll
                for (int nt = 0; nt < 4; nt++) {
                    mma16816(acc[mt][nt], ah[mt], bh[nt]);
                    mma16816(acc[mt][nt], ah[mt], bl[nt]);
                    mma16816(acc[mt][nt], al[mt], bh[nt]);
                }
        }
        __syncthreads();
    }

#pragma unroll
    for (int mt = 0; mt < 4; mt++) {
#pragma unroll
        for (int nt = 0; nt < 4; nt++) {
            const int row = row0 + wm * 64 + mt * 16 + (lane >> 2);
            const int col = col0 + wn * 32 + nt * 8 + (lane & 3) * 2;
            float v0 = acc[mt][nt][0];
            float v1 = acc[mt][nt][1];
            float v2 = acc[mt][nt][2];
            float v3 = acc[mt][nt][3];
            if (MODE == 0) {
                const long long o0 = (long long)row * ldc + col;
                const long long o1 = o0 + 8LL * ldc;
                if (bias) {
                    float b0 = __ldg(bias + col), b1 = __ldg(bias + col + 1);
                    v0 += b0; v1 += b1; v2 += b0; v3 += b1;
                }
                if (Res) {
                    float2 r0 = *reinterpret_cast<const float2*>(Res + o0);
                    float2 r1 = *reinterpret_cast<const float2*>(Res + o1);
                    v0 += r0.x; v1 += r0.y; v2 += r1.x; v3 += r1.y;
                }
                *reinterpret_cast<float2*>(Cf + o0) = make_float2(v0, v1);
                *reinterpret_cast<float2*>(Cf + o1) = make_float2(v2, v3);
            } else {
                // cols interleaved: even col = gate_j, odd = up_j, j = col/2
                const int j = col >> 1;
                const long long o0 = (long long)row * ldc + j;
                const long long o1 = o0 + 8LL * ldc;
                float r0 = v0 / (1.f + expf(-v0)) * v1;
                float r2 = v2 / (1.f + expf(-v2)) * v3;
                bf16 h, l;
                split_bf16(r0, h, l); Chi[o0] = h; Clo[o0] = l;
                split_bf16(r2, h, l); Chi[o1] = h; Clo[o1] = l;
            }
        }
    }
}

// ---------------- flash attention (fused QK^T -> softmax -> PV) ----------------
// Pairing for causal balance: CTA p handles q-blocks [64p, 64p+64) (warps 0-3) and
// [960-64p, 1024-64p) (warps 4-7). Work = (17+p)+(32-p) = 49 tiles, constant.
// K/V tiles shared by both halves. Warps past their own causal range skip compute.
#define TkF   64
#define QSTRB 272                   // Q/K smem row stride bytes (136 bf16)
#define VSTRB 144                   // V smem row stride bytes (72 bf16)
#define QPL   (128 * QSTRB)
#define KPL   (64 * QSTRB)
#define VPL   (128 * VSTRB)
#define FSTG  (2 * KPL + 2 * VPL)
#define FKOFF (2 * QPL)
#define FSMEM (FKOFF + 2 * FSTG)    // 212992

__global__ void __launch_bounds__(256, 1)
flash_kernel(const bf16* __restrict__ qhp, const bf16* __restrict__ qlp,
             const bf16* __restrict__ khp, const bf16* __restrict__ klp,
             const bf16* __restrict__ vthp, const bf16* __restrict__ vtlp,
             bf16* __restrict__ ohp, bf16* __restrict__ olp)
{
    extern __shared__ char smc[];
    const uint32_t smb = smem_u32(smc);
    const int tid = threadIdx.x, lane = tid & 31, wid = tid >> 5;
    const int pp = blockIdx.x, h = blockIdx.y;       // pair index 0..7
    const int baseA = 64 * pp;
    const int baseB = 960 - 64 * pp;
    const int kvh = h >> 3;
    const int nkt = 32 - pp;                          // group-B (max) tile count
    const int wg = wid >> 2;                          // 0 = block A, 1 = block B
    const int my_nkt = wg ? nkt : 17 + pp;            // group-A stops early

    // Q tile: smem rows 0-63 = block A, 64-127 = block B
    for (int c = tid; c < 2048; c += 256) {
        const int r = c >> 4, sg = c & 15;
        const int grow = (r < 64) ? (baseA + r) : (baseB + r - 64);
        const uint32_t d = smb + r * QSTRB + sg * 16;
        const size_t src = (size_t)grow * Hn + h * HDn + sg * 8;
        cpa16(d, qhp + src);
        cpa16(d + QPL, qlp + src);
    }
    cp_commit();

    auto load_kv = [&](int kt) {
        const int t0 = kt * TkF;
        const uint32_t base = smb + FKOFF + (kt & 1) * FSTG;
        for (int c = tid; c < 1024; c += 256) {
            const int r = c >> 4, sg = c & 15;
            const uint32_t d = base + r * QSTRB + sg * 16;
            const size_t src = ((size_t)kvh * Tn + t0 + r) * HDn + sg * 8;
            cpa16(d, khp + src);
            cpa16(d + KPL, klp + src);
        }
        for (int c = tid; c < 1024; c += 256) {
            const int r = c >> 3, sg = c & 7;
            const uint32_t d = base + 2 * KPL + r * VSTRB + sg * 16;
            const size_t src = ((size_t)kvh * HDn + r) * Tn + t0 + sg * 8;
            cpa16(d, vthp + src);
            cpa16(d + VPL, vtlp + src);
        }
    };
    load_kv(0); cp_commit();

    float O[16][4];
#pragma unroll
    for (int i = 0; i < 16; i++)
#pragma unroll
        for (int e = 0; e < 4; e++) O[i][e] = 0.f;
    float m1 = -1e30f, m2 = -1e30f, l1 = 0.f, l2 = 0.f;

    const int qrow1 = (wg ? baseB : baseA) + (wid & 3) * 16 + (lane >> 2);
    const int lim1 = Pn + qrow1;
    const int lim2 = lim1 + 8;

    const uint32_t qbase = smb +
        (wid * 16 + ((lane >> 3) & 1) * 8 + (lane & 7)) * QSTRB + ((lane >> 4) & 1) * 16;
    const uint32_t brow = ((lane >> 4) & 1) * 8 + (lane & 7);
    const uint32_t bcol = ((lane >> 3) & 1) * 16;

    for (int kt = 0; kt < nkt; kt++) {
        if (kt + 1 < nkt) { load_kv(kt + 1); cp_commit(); cp_wait1(); }
        else cp_wait0();
        __syncthreads();
        const uint32_t base = smb + FKOFF + (kt & 1) * FSTG;

        if (kt < my_nkt) {
            float S[8][4];
#pragma unroll
            for (int nt = 0; nt < 8; nt++)
#pragma unroll
                for (int e = 0; e < 4; e++) S[nt][e] = 0.f;
#pragma unroll
            for (int ks = 0; ks < 8; ks++) {
                uint32_t qa_h[4], qa_l[4];
                ldm4(qa_h, qbase + ks * 32);
                ldm4(qa_l, qbase + ks * 32 + QPL);
#pragma unroll
                for (int p = 0; p < 4; p++) {
                    uint32_t rh[4], rl[4];
                    const uint32_t a = base + (p * 16 + brow) * QSTRB + ks * 32 + bcol;
                    ldm4(rh, a);
                    ldm4(rl, a + KPL);
                    uint32_t bh0[2] = {rh[0], rh[1]}, bh1[2] = {rh[2], rh[3]};
                    uint32_t bl0[2] = {rl[0], rl[1]}, bl1[2] = {rl[2], rl[3]};
                    mma16816(S[2*p],   qa_h, bh0); mma16816(S[2*p],   qa_h, bl0); mma16816(S[2*p],   qa_l, bh0);
                    mma16816(S[2*p+1], qa_h, bh1); mma16816(S[2*p+1], qa_h, bl1); mma16816(S[2*p+1], qa_l, bh1);
                }
            }

            const int t0 = kt * TkF;
            float mx1 = -1e30f, mx2 = -1e30f;
#pragma unroll
            for (int nt = 0; nt < 8; nt++) {
                const int tb = t0 + nt * 8 + (lane & 3) * 2;
#pragma unroll
                for (int e = 0; e < 2; e++) {
                    S[nt][e]     = (tb + e <= lim1) ? S[nt][e]     * SCALEn : -1e30f;
                    S[nt][2 + e] = (tb + e <= lim2) ? S[nt][2 + e] * SCALEn : -1e30f;
                    mx1 = fmaxf(mx1, S[nt][e]);
                    mx2 = fmaxf(mx2, S[nt][2 + e]);
                }
            }
            mx1 = fmaxf(mx1, __shfl_xor_sync(~0u, mx1, 1));
            mx1 = fmaxf(mx1, __shfl_xor_sync(~0u, mx1, 2));
            mx2 = fmaxf(mx2, __shfl_xor_sync(~0u, mx2, 1));
            mx2 = fmaxf(mx2, __shfl_xor_sync(~0u, mx2, 2));
            const float mn1 = fmaxf(m1, mx1), mn2 = fmaxf(m2, mx2);
            const float sc1 = __expf(fmaxf(m1 - mn1, -80.f));
            const float sc2 = __expf(fmaxf(m2 - mn2, -80.f));
            m1 = mn1; m2 = mn2;
            float rs1 = 0.f, rs2 = 0.f;
#pragma unroll
            for (int nt = 0; nt < 8; nt++) {
                S[nt][0] = __expf(fmaxf(S[nt][0] - mn1, -80.f));
                S[nt][1] = __expf(fmaxf(S[nt][1] - mn1, -80.f));
                S[nt][2] = __expf(fmaxf(S[nt][2] - mn2, -80.f));
                S[nt][3] = __expf(fmaxf(S[nt][3] - mn2, -80.f));
                rs1 += S[nt][0] + S[nt][1];
                rs2 += S[nt][2] + S[nt][3];
            }
            rs1 += __shfl_xor_sync(~0u, rs1, 1); rs1 += __shfl_xor_sync(~0u, rs1, 2);
            rs2 += __shfl_xor_sync(~0u, rs2, 1); rs2 += __shfl_xor_sync(~0u, rs2, 2);
            l1 = l1 * sc1 + rs1;
            l2 = l2 * sc2 + rs2;
#pragma unroll
            for (int i = 0; i < 16; i++) {
                O[i][0] *= sc1; O[i][1] *= sc1; O[i][2] *= sc2; O[i][3] *= sc2;
            }

#pragma unroll
            for (int ks2 = 0; ks2 < 4; ks2++) {
                uint32_t pa_h[4], pa_l[4];
#pragma unroll
                for (int half = 0; half < 2; half++) {
                    const int nt = 2 * ks2 + half;
                    bf16 h0, g0, h1, g1, h2, g2, h3, g3;
                    split_bf16(S[nt][0], h0, g0); split_bf16(S[nt][1], h1, g1);
                    split_bf16(S[nt][2], h2, g2); split_bf16(S[nt][3], h3, g3);
                    pa_h[half ? 2 : 0] = b2u(__nv_bfloat162(h0, h1));
                    pa_h[half ? 3 : 1] = b2u(__nv_bfloat162(h2, h3));
                    pa_l[half ? 2 : 0] = b2u(__nv_bfloat162(g0, g1));
                    pa_l[half ? 3 : 1] = b2u(__nv_bfloat162(g2, g3));
                }
#pragma unroll
                for (int p2 = 0; p2 < 8; p2++) {
                    uint32_t rv[4], rvl[4];
                    const uint32_t a = base + 2 * KPL + (p2 * 16 + brow) * VSTRB + ks2 * 32 + bcol;
                    ldm4(rv, a);
                    ldm4(rvl, a + VPL);
                    uint32_t b0[2] = {rv[0], rv[1]},  b1[2] = {rv[2], rv[3]};
                    uint32_t c0[2] = {rvl[0], rvl[1]}, c1[2] = {rvl[2], rvl[3]};
                    mma16816(O[2*p2],   pa_h, b0); mma16816(O[2*p2],   pa_h, c0); mma16816(O[2*p2],   pa_l, b0);
                    mma16816(O[2*p2+1], pa_h, b1); mma16816(O[2*p2+1], pa_h, c1); mma16816(O[2*p2+1], pa_l, b1);
                }
            }
        }
        __syncthreads();
    }

    const float inv1 = 1.f / l1, inv2 = 1.f / l2;
    const int r1 = qrow1, r2 = qrow1 + 8;
    const int colb = h * HDn + (lane & 3) * 2;
#pragma unroll
    for (int nt2 = 0; nt2 < 16; nt2++) {
        const int col = colb + nt2 * 8;
        bf16 a0, b0, a1, b1;
        split_bf16(O[nt2][0] * inv1, a0, b0);
        split_bf16(O[nt2][1] * inv1, a1, b1);
        *reinterpret_cast<uint32_t*>(ohp + (size_t)r1 * Hn + col) = b2u(__nv_bfloat162(a0, a1));
        *reinterpret_cast<uint32_t*>(olp + (size_t)r1 * Hn + col) = b2u(__nv_bfloat162(b0, b1));
        split_bf16(O[nt2][2] * inv2, a0, b0);
        split_bf16(O[nt2][3] * inv2, a1, b1);
        *reinterpret_cast<uint32_t*>(ohp + (size_t)r2 * Hn + col) = b2u(__nv_bfloat162(a0, a1));
        *reinterpret_cast<uint32_t*>(olp + (size_t)r2 * Hn + col) = b2u(__nv_bfloat162(b0, b1));
    }
}

// ---------------- weight transpose + split: in[K,N] fp32 -> out[N*rmul+roff, K] bf16 hi/lo ----
struct __align__(16) B8 { bf16 v[8]; };

__global__ void __launch_bounds__(256)
convT_kernel(const float* __restrict__ in, bf16* __restrict__ hi, bf16* __restrict__ lo,
             int K, int N, int rmul, int roff)
{
    __shared__ float s[32][129];
    const int n0 = blockIdx.x * 128, k0 = blockIdx.y * 32;
    const int t = threadIdx.x;
    const int r = t >> 5, c4 = (t & 31) * 4;
    float4 v[4];
#pragma unroll
    for (int rr = 0; rr < 4; rr++)
        v[rr] = *reinterpret_cast<const float4*>(in + (size_t)(k0 + r + rr * 8) * N + n0 + c4);
#pragma unroll
    for (int rr = 0; rr < 4; rr++) {
        const int k = r + rr * 8;
        s[k][c4] = v[rr].x; s[k][c4+1] = v[rr].y; s[k][c4+2] = v[rr].z; s[k][c4+3] = v[rr].w;
    }
    __syncthreads();
    const int n = t >> 1, kk0 = (t & 1) * 16;
    B8 hb[2], lb[2];
#pragma unroll
    for (int kk = 0; kk < 16; kk++) {
        bf16 h, l;
        split_bf16(s[kk0 + kk][n], h, l);
        hb[kk >> 3].v[kk & 7] = h;
        lb[kk >> 3].v[kk & 7] = l;
    }
    const size_t o = (size_t)((n0 + n) * rmul + roff) * K + k0 + kk0;
    *reinterpret_cast<B8*>(hi + o)     = hb[0];
    *reinterpret_cast<B8*>(hi + o + 8) = hb[1];
    *reinterpret_cast<B8*>(lo + o)     = lb[0];
    *reinterpret_cast<B8*>(lo + o + 8) = lb[1];
}

// ---------------- pack QKV biases into one 2560-vector ----------------
__global__ void packbias_kernel(const float* __restrict__ bq, const float* __restrict__ bk,
                                const float* __restrict__ bv, float* __restrict__ o)
{
    int i = blockIdx.x * 256 + threadIdx.x;
    if (i < 2048) o[i] = bq[i];
    else if (i < 2304) o[i] = bk[i - 2048];
    else if (i < 2560) o[i] = bv[i - 2304];
}

// ---------------- RMSNorm: MODE 0 -> fp32 out, MODE 1 -> bf16 hi/lo ----------------
template<int MODE>
__global__ void __launch_bounds__(256)
rmsnorm_kernel(const float* __restrict__ x, const float* __restrict__ w,
               float* __restrict__ yf, bf16* __restrict__ yh, bf16* __restrict__ yl)
{
    int s = blockIdx.x;
    const float* row = x + (size_t)s * Hn;
    float4 buf[2];
    float ss = 0.f;
#pragma unroll
    for (int it = 0; it < 2; it++) {
        int j = (it * 256 + threadIdx.x) * 4;
        float4 v = *reinterpret_cast<const float4*>(row + j);
        buf[it] = v;
        ss += v.x * v.x + v.y * v.y + v.z * v.z + v.w * v.w;
    }
    ss = blockSum256(ss);
    float inv = rsqrtf(ss * (1.0f / Hn) + EPSn);
#pragma unroll
    for (int it = 0; it < 2; it++) {
        int j = (it * 256 + threadIdx.x) * 4;
        float4 wv = *reinterpret_cast<const float4*>(w + j);
        float o0 = buf[it].x * inv * wv.x;
        float o1 = buf[it].y * inv * wv.y;
        float o2 = buf[it].z * inv * wv.z;
        float o3 = buf[it].w * inv * wv.w;
        if (MODE == 0) {
            *reinterpret_cast<float4*>(yf + (size_t)s * Hn + j) = make_float4(o0, o1, o2, o3);
        } else {
            bf16 h0,l0,h1,l1,h2,l2,h3,l3;
            split_bf16(o0,h0,l0); split_bf16(o1,h1,l1);
            split_bf16(o2,h2,l2); split_bf16(o3,h3,l3);
            __nv_bfloat162 hh0(h0,h1), hh1(h2,h3), ll0(l0,l1), ll1(l2,l3);
            uint2 uh = make_uint2(b2u(hh0), b2u(hh1));
            uint2 ul = make_uint2(b2u(ll0), b2u(ll1));
            *reinterpret_cast<uint2*>(yh + (size_t)s * Hn + j) = uh;
            *reinterpret_cast<uint2*>(yl + (size_t)s * Hn + j) = ul;
        }
    }
}

// ---------------- RoPE for Q: fp32 (strided in qkv) -> bf16 hi/lo dense [S,2048] ----------------
__global__ void rope_q_kernel(const float* __restrict__ qkv, const int* __restrict__ pos,
                              bf16* __restrict__ qh, bf16* __restrict__ ql)
{
    int s = blockIdx.x, h = blockIdx.y, d = threadIdx.x; // d in [0,64)
    double ang = (double)pos[s] * exp(-(double)d / 64.0 * 13.815510557964274);
    double sd, cd; sincos(ang, &sd, &cd);
    float c = (float)cd, sn = (float)sd;
    size_t ibase = (size_t)s * 2560 + h * HDn;
    size_t obase = ((size_t)s * NHn + h) * HDn;
    float x1 = qkv[ibase + d], x2 = qkv[ibase + d + 64];
    float v1 = x1 * c - x2 * sn;
    float v2 = x2 * c + x1 * sn;
    bf16 hh, ll;
    split_bf16(v1, hh, ll); qh[obase + d] = hh;      ql[obase + d] = ll;
    split_bf16(v2, hh, ll); qh[obase + d + 64] = hh; ql[obase + d + 64] = ll;
}

// ---------------- K/V cache: tiled 32t x 128d; coalesced transposed V via smem ----------------
__global__ void __launch_bounds__(256)
kv_cache_kernel(const float* __restrict__ qkv,
                const float* __restrict__ pastk, const float* __restrict__ pastv,
                const int* __restrict__ pos,
                float* __restrict__ kc, float* __restrict__ vc,
                bf16* __restrict__ kh, bf16* __restrict__ kl,
                bf16* __restrict__ vth, bf16* __restrict__ vtl)
{
    __shared__ float sv[32][129];
    const int t0 = blockIdx.x * 32, kv = blockIdx.y;
    const int tid = threadIdx.x;

    // phase 1: compute k/v, write k planes + fp32 caches (coalesced over d)
#pragma unroll
    for (int i = 0; i < 16; i++) {
        const int idx = i * 256 + tid;          // 0..4095
        const int tt = idx >> 7, d = idx & 127;
        const int t = t0 + tt;
        float kval, vval;
        if (t < Pn) {
            size_t pidx = ((size_t)kv * Pn + t) * HDn + d;
            kval = pastk[pidx];
            vval = pastv[pidx];
        } else {
            int s = t - Pn;
            const float* kr = qkv + (size_t)s * 2560 + 2048 + kv * HDn;
            int dr = d & 63;
            double ang = (double)pos[s] * exp(-(double)dr / 64.0 * 13.815510557964274);
            double sd, cd; sincos(ang, &sd, &cd);
            float c = (float)cd, sn = (float)sd;
            if (d < 64) kval = kr[d] * c - kr[d + 64] * sn;
            else        kval = kr[d] * c + kr[d - 64] * sn;
            vval = qkv[(size_t)s * 2560 + 2304 + kv * HDn + d];
        }
        size_t oidx = ((size_t)kv * Tn + t) * HDn + d;
        kc[oidx] = kval;
        vc[oidx] = vval;
        bf16 h, l;
        split_bf16(kval, h, l);
        kh[oidx] = h; kl[oidx] = l;
        sv[tt][d] = vval;
    }
    __syncthreads();

    // phase 2: transposed V planes, lanes walk t (coalesced)
    const int tt = tid & 31, dw = tid >> 5;     // warp handles one d per pass
#pragma unroll
    for (int d0 = 0; d0 < 128; d0 += 8) {
        const int d = d0 + dw;
        bf16 h, l;
        split_bf16(sv[tt][d], h, l);
        size_t o = ((size_t)kv * HDn + d) * Tn + t0 + tt;
        vth[o] = h; vtl[o] = l;
    }
}

// ---------------- host-side launch helpers ----------------
static void mmagemm(const bf16* Ah, const bf16* Al, const bf16* Bh, const bf16* Bl,
                    const float* bias, const float* Res, float* Cf,
                    int M, int N, int K, int lda, int ldb, int ldc)
{
    dim3 grid(N / 128, M / 128, 1);
    mma_gemm<0><<<grid, 256, NSTAGE * STAGEB>>>(Ah, Al, Bh, Bl, bias, Res, Cf,
                                                nullptr, nullptr, K, lda, ldb, ldc);
}
static void mmagemm_gu(const bf16* Ah, const bf16* Al, const bf16* Bh, const bf16* Bl,
                       bf16* Chi, bf16* Clo, int M, int N, int K, int lda, int ldb, int ldc)
{
    dim3 grid(N / 128, M / 128, 1);
    mma_gemm<1><<<grid, 256, NSTAGE * STAGEB>>>(Ah, Al, Bh, Bl, nullptr, nullptr, nullptr,
                                                Chi, Clo, K, lda, ldb, ldc);
}

extern "C" void kernel_launch(void* const* d_in, const int* in_sizes, int n_in,
                              void* d_out, int out_size)
{
    (void)in_sizes; (void)n_in; (void)out_size;
    const float* embeds = (const float*)d_in[0];
    const int*   pos    = (const int*)  d_in[1];
    const float* past_k = (const float*)d_in[2];
    const float* past_v = (const float*)d_in[3];
    const float* ln1    = (const float*)d_in[4];
    const float* wq     = (const float*)d_in[5];
    const float* bq     = (const float*)d_in[6];
    const float* wk     = (const float*)d_in[7];
    const float* bk     = (const float*)d_in[8];
    const float* wv     = (const float*)d_in[9];
    const float* bv     = (const float*)d_in[10];
    const float* wo     = (const float*)d_in[11];
    const float* ln2    = (const float*)d_in[12];
    const float* wg     = (const float*)d_in[13];
    const float* wu     = (const float*)d_in[14];
    const float* wd     = (const float*)d_in[15];
    const float* normw  = (const float*)d_in[16];
    float* out = (float*)d_out;

    cudaFuncSetAttribute(mma_gemm<0>, cudaFuncAttributeMaxDynamicSharedMemorySize, NSTAGE * STAGEB);
    cudaFuncSetAttribute(mma_gemm<1>, cudaFuncAttributeMaxDynamicSharedMemorySize, NSTAGE * STAGEB);
    cudaFuncSetAttribute(flash_kernel, cudaFuncAttributeMaxDynamicSharedMemorySize, FSMEM);

    float *hid, *qkv, *bqkv;
    cudaGetSymbolAddress((void**)&hid,  g_hid);
    cudaGetSymbolAddress((void**)&qkv,  g_qkv);
    cudaGetSymbolAddress((void**)&bqkv, g_bqkv);
    bf16 *hnh,*hnl,*qh,*ql,*kh,*kl,*vth,*vtl,*ath,*atl,*gh,*gl,*wh,*wl;
    cudaGetSymbolAddress((void**)&hnh, g_hn_hi); cudaGetSymbolAddress((void**)&hnl, g_hn_lo);
    cudaGetSymbolAddress((void**)&qh,  g_q_hi);  cudaGetSymbolAddress((void**)&ql,  g_q_lo);
    cudaGetSymbolAddress((void**)&kh,  g_k_hi);  cudaGetSymbolAddress((void**)&kl,  g_k_lo);
    cudaGetSymbolAddress((void**)&vth, g_vt_hi); cudaGetSymbolAddress((void**)&vtl, g_vt_lo);
    cudaGetSymbolAddress((void**)&ath, g_at_hi); cudaGetSymbolAddress((void**)&atl, g_at_lo);
    cudaGetSymbolAddress((void**)&gh,  g_g_hi);  cudaGetSymbolAddress((void**)&gl,  g_g_lo);
    cudaGetSymbolAddress((void**)&wh,  g_w_hi);  cudaGetSymbolAddress((void**)&wl,  g_w_lo);

    // per-layer offsets into transposed weight store
    // [OQ: qkv 2560 rows][OO: wo 2048 rows][OG: gate/up interleaved 11264 rows][OD: wd 2048 rows]
    const long long OQ = 0, OO = 5242880, OG = 9437184, OD = 32505856;
    const long long OK_ = 4194304, OV = 4718592;

    // ---- transpose + split all weights ----
    dim3 cb(256);
    for (int l = 0; l < Ln; l++) {
        long long base = (long long)l * WL;
        convT_kernel<<<dim3(2048/128, 2048/32), cb>>>(wq + (size_t)l*Hn*2048, wh + base + OQ,  wl + base + OQ,  Hn, 2048, 1, 0);
        convT_kernel<<<dim3(256/128,  2048/32), cb>>>(wk + (size_t)l*Hn*256,  wh + base + OK_, wl + base + OK_, Hn, 256, 1, 0);
        convT_kernel<<<dim3(256/128,  2048/32), cb>>>(wv + (size_t)l*Hn*256,  wh + base + OV,  wl + base + OV,  Hn, 256, 1, 0);
        convT_kernel<<<dim3(2048/128, 2048/32), cb>>>(wo + (size_t)l*Hn*Hn,   wh + base + OO,  wl + base + OO,  Hn, 2048, 1, 0);
        convT_kernel<<<dim3(5632/128, 2048/32), cb>>>(wg + (size_t)l*Hn*FFn,  wh + base + OG,  wl + base + OG,  Hn, FFn, 2, 0);
        convT_kernel<<<dim3(5632/128, 2048/32), cb>>>(wu + (size_t)l*Hn*FFn,  wh + base + OG,  wl + base + OG,  Hn, FFn, 2, 1);
        convT_kernel<<<dim3(2048/128, 5632/32), cb>>>(wd + (size_t)l*FFn*Hn,  wh + base + OD,  wl + base + OD,  FFn, 2048, 1, 0);
    }

    cudaMemcpyAsync(hid, embeds, sizeof(float) * Sn * Hn, cudaMemcpyDeviceToDevice);

    for (int l = 0; l < Ln; l++) {
        long long base = (long long)l * WL;
        float* kc = out + (size_t)Sn * Hn + (size_t)l * 2 * NKVn * Tn * HDn;
        float* vc = kc + (size_t)NKVn * Tn * HDn;

        // pre-attention norm -> bf16 hi/lo
        rmsnorm_kernel<1><<<Sn, 256>>>(hid, ln1 + (size_t)l * Hn, nullptr, hnh, hnl);

        // fused QKV projection (N=2560) -> fp32 qkv buffer
        packbias_kernel<<<10, 256>>>(bq + (size_t)l*2048, bk + (size_t)l*256, bv + (size_t)l*256, bqkv);
        mmagemm(hnh, hnl, wh + base + OQ, wl + base + OQ, bqkv, nullptr,
                qkv, Sn, 2560, Hn, Hn, Hn, 2560);

        // RoPE Q -> bf16 hi/lo; KV cache (fp32 to d_out + bf16 hi/lo, V transposed)
        rope_q_kernel<<<dim3(Sn, NHn), 64>>>(qkv, pos, qh, ql);
        kv_cache_kernel<<<dim3(Tn / 32, NKVn), 256>>>(
            qkv,
            past_k + (size_t)l * NKVn * Pn * HDn,
            past_v + (size_t)l * NKVn * Pn * HDn,
            pos, kc, vc, kh, kl, vth, vtl);

        // fused attention (paired causal blocks): QK^T -> online softmax -> PV
        flash_kernel<<<dim3(8, NHn), 256, FSMEM>>>(qh, ql, kh, kl, vth, vtl, ath, atl);

        // output projection + residual (fp32)
        mmagemm(ath, atl, wh + base + OO, wl + base + OO, nullptr, hid,
                hid, Sn, Hn, Hn, Hn, Hn, Hn);

        // MLP: gate|up interleaved GEMM with fused SiLU epilogue -> bf16 hi/lo, then down
        rmsnorm_kernel<1><<<Sn, 256>>>(hid, ln2 + (size_t)l * Hn, nullptr, hnh, hnl);
        mmagemm_gu(hnh, hnl, wh + base + OG, wl + base + OG, gh, gl,
                   Sn, 2*FFn, Hn, Hn, Hn, FFn);
        mmagemm(gh, gl, wh + base + OD, wl + base + OD, nullptr, hid,
                hid, Sn, Hn, FFn, FFn, FFn, Hn);
    }

    // final norm -> fp32 hidden output
    rmsnorm_kernel<0><<<Sn, 256>>>(hid, normw, out, nullptr, nullptr);
}

// round 15
// speedup vs baseline: 1.1073x; 1.0332x over previous
#include <cuda_runtime.h>
#include <cuda_bf16.h>
#include <math.h>
#include <stdint.h>

// ---------------- problem constants ----------------
#define Ln   2
#define Hn   2048
#define NHn  16
#define NKVn 2
#define HDn  128
#define Sn   1024
#define Pn   1024
#define FFn  5632
#define Tn   (Pn + Sn)       // 2048
#define Gn   (NHn / NKVn)    // 8
#define EPSn 1e-6f
#define SCALEn 0.08838834764831845f  // 1/sqrt(128)

typedef __nv_bfloat16 bf16;

// ---------------- device scratch (static, no allocation) ----------------
static __device__ float g_hid   [Sn * Hn];
static __device__ float g_qkv   [Sn * 2560];
static __device__ float g_bqkv  [2560];

static __device__ bf16 g_hn_hi[Sn * Hn],  g_hn_lo[Sn * Hn];
static __device__ bf16 g_q_hi [Sn * Hn],  g_q_lo [Sn * Hn];
static __device__ bf16 g_k_hi [NKVn * Tn * HDn], g_k_lo [NKVn * Tn * HDn];
static __device__ bf16 g_vt_hi[NKVn * HDn * Tn], g_vt_lo[NKVn * HDn * Tn];
static __device__ bf16 g_at_hi[Sn * Hn],  g_at_lo[Sn * Hn];
static __device__ bf16 g_g_hi [(size_t)Sn * FFn], g_g_lo [(size_t)Sn * FFn];

// transposed+split weights: per layer [wq(2048x2048), wk(256x2048), wv(256x2048),
//  wo(2048x2048), gu_interleaved(11264x2048), wd(2048x5632)]  (all [N,K])
#define WL 44040192LL
#define WTOT (2 * WL)
static __device__ bf16 g_w_hi[WTOT], g_w_lo[WTOT];

// ---------------- small helpers ----------------
__device__ __forceinline__ float warpSum(float v) {
#pragma unroll
    for (int o = 16; o; o >>= 1) v += __shfl_xor_sync(0xffffffffu, v, o);
    return v;
}
__device__ float blockSum256(float v) {
    __shared__ float sm[8]; __shared__ float res;
    v = warpSum(v);
    if ((threadIdx.x & 31) == 0) sm[threadIdx.x >> 5] = v;
    __syncthreads();
    float w = (threadIdx.x < 8) ? sm[threadIdx.x] : 0.f;
    w = warpSum(w);
    if (threadIdx.x == 0) res = w;
    __syncthreads();
    return res;
}

__device__ __forceinline__ void split_bf16(float x, bf16& h, bf16& l) {
    h = __float2bfloat16(x);
    l = __float2bfloat16(x - __bfloat162float(h));
}
__device__ __forceinline__ uint32_t b2u(__nv_bfloat162 v) {
    return *reinterpret_cast<uint32_t*>(&v);
}

// ---------------- PTX wrappers (plain sm_80+ features only) ----------------
__device__ __forceinline__ uint32_t smem_u32(const void* p) {
    uint32_t a;
    asm("{ .reg .u64 t; cvta.to.shared.u64 t, %1; cvt.u32.u64 %0, t; }" : "=r"(a) : "l"(p));
    return a;
}
__device__ __forceinline__ void cpa16(uint32_t d, const void* s) {
    asm volatile("cp.async.cg.shared.global [%0], [%1], 16;" :: "r"(d), "l"(s));
}
__device__ __forceinline__ void cp_commit() {
    asm volatile("cp.async.commit_group;" ::: "memory");
}
__device__ __forceinline__ void cp_wait2() {
    asm volatile("cp.async.wait_group 2;" ::: "memory");
}
__device__ __forceinline__ void cp_wait1() {
    asm volatile("cp.async.wait_group 1;" ::: "memory");
}
__device__ __forceinline__ void cp_wait0() {
    asm volatile("cp.async.wait_group 0;" ::: "memory");
}
__device__ __forceinline__ void ldm4(uint32_t* r, uint32_t a) {
    asm volatile("ldmatrix.sync.aligned.m8n8.x4.shared.b16 {%0,%1,%2,%3}, [%4];"
        : "=r"(r[0]), "=r"(r[1]), "=r"(r[2]), "=r"(r[3]) : "r"(a));
}
__device__ __forceinline__ void mma16816(float* c, const uint32_t* a, const uint32_t* b) {
    asm volatile(
        "mma.sync.aligned.m16n8k16.row.col.f32.bf16.bf16.f32 "
        "{%0,%1,%2,%3}, {%4,%5,%6,%7}, {%8,%9}, {%0,%1,%2,%3};"
        : "+f"(c[0]), "+f"(c[1]), "+f"(c[2]), "+f"(c[3])
        : "r"(a[0]), "r"(a[1]), "r"(a[2]), "r"(a[3]), "r"(b[0]), "r"(b[1]));
}

// ---------------- tensor-core GEMM (mma.sync bf16, 3-way split, 3-stage pipe) ----------------
// C[M,N] = A[M,K] @ B[N,K]^T. A/B are bf16 hi/lo pairs.
// MODE 0: fp32 out (+bias)(+Res).  MODE 1: gate/up interleaved cols -> silu(g)*u, bf16 hi/lo
//         out at [row, col/2] with row stride ldc.
#define AST  40                        // smem row stride in bf16 (80 B)
#define TILEB (128 * AST * 2)          // 10240 B per plane
#define STAGEB (4 * TILEB)             // Ah, Al, Bh, Bl
#define NSTAGE 3

template<int MODE>
__global__ void __launch_bounds__(256, 1)
mma_gemm(const bf16* __restrict__ Ah, const bf16* __restrict__ Al,
         const bf16* __restrict__ Bh, const bf16* __restrict__ Bl,
         const float* __restrict__ bias, const float* __restrict__ Res,
         float* __restrict__ Cf, bf16* __restrict__ Chi, bf16* __restrict__ Clo,
         int K, int lda, int ldb, int ldc)
{
    extern __shared__ char smc[];
    const int tid = threadIdx.x;
    const int lane = tid & 31;
    const int wid = tid >> 5;
    const int wm = wid >> 2;           // 0..1
    const int wn = wid & 3;            // 0..3
    const int row0 = blockIdx.y * 128;
    const int col0 = blockIdx.x * 128;

    const uint32_t smb = smem_u32(smc);

    float acc[4][4][4];
#pragma unroll
    for (int i = 0; i < 4; i++)
#pragma unroll
        for (int j = 0; j < 4; j++)
#pragma unroll
            for (int e = 0; e < 4; e++) acc[i][j][e] = 0.f;

    const int nk = K >> 5;

    auto load_tile = [&](int i) {
        const int k0 = i << 5;
        const uint32_t sb = smb + (i % NSTAGE) * STAGEB;
#pragma unroll
        for (int c = tid; c < 512; c += 256) {
            const int r = c >> 2, sg = c & 3;
            const uint32_t d = sb + r * (AST * 2) + sg * 16;
            const size_t ga = (size_t)(row0 + r) * lda + k0 + sg * 8;
            const size_t gb = (size_t)(col0 + r) * ldb + k0 + sg * 8;
            cpa16(d,             Ah + ga);
            cpa16(d + TILEB,     Al + ga);
            cpa16(d + 2 * TILEB, Bh + gb);
            cpa16(d + 3 * TILEB, Bl + gb);
        }
    };

    load_tile(0); cp_commit();
    load_tile(1); cp_commit();

    for (int i = 0; i < nk; i++) {
        if (i + 2 < nk) { load_tile(i + 2); cp_commit(); cp_wait2(); }
        else if (i + 1 < nk) cp_wait1();
        else cp_wait0();
        __syncthreads();

        const uint32_t sb = smb + (i % NSTAGE) * STAGEB;
#pragma unroll
        for (int ks = 0; ks < 2; ks++) {
            uint32_t ah[4][4], al[4][4], bh[4][2], bl[4][2];
            const int acol = ks * 32 + ((lane >> 4) & 1) * 16;
#pragma unroll
            for (int mt = 0; mt < 4; mt++) {
                const int row = wm * 64 + mt * 16 + ((lane >> 3) & 1) * 8 + (lane & 7);
                const uint32_t a = sb + row * (AST * 2) + acol;
                ldm4(ah[mt], a);
                ldm4(al[mt], a + TILEB);
            }
            const int bcol = ks * 32 + ((lane >> 3) & 1) * 16;
#pragma unroll
            for (int p = 0; p < 2; p++) {
                const int row = wn * 32 + p * 16 + ((lane >> 4) & 1) * 8 + (lane & 7);
                const uint32_t a = sb + 2 * TILEB + row * (AST * 2) + bcol;
                uint32_t r[4];
                ldm4(r, a);
                bh[2*p][0] = r[0]; bh[2*p][1] = r[1];
                bh[2*p+1][0] = r[2]; bh[2*p+1][1] = r[3];
                ldm4(r, a + TILEB);
                bl[2*p][0] = r[0]; bl[2*p][1] = r[1];
                bl[2*p+1][0] = r[2]; bl[2*p+1][1] = r[3];
            }
#pragma unroll
            for (int mt = 0; mt < 4; mt++)
#pragma unroll
                for (int nt = 0; nt < 4; nt++) {
                    mma16816(acc[mt][nt], ah[mt], bh[nt]);
                    mma16816(acc[mt][nt], ah[mt], bl[nt]);
                    mma16816(acc[mt][nt], al[mt], bh[nt]);
                }
        }
        __syncthreads();
    }

#pragma unroll
    for (int mt = 0; mt < 4; mt++) {
#pragma unroll
        for (int nt = 0; nt < 4; nt++) {
            const int row = row0 + wm * 64 + mt * 16 + (lane >> 2);
            const int col = col0 + wn * 32 + nt * 8 + (lane & 3) * 2;
            float v0 = acc[mt][nt][0];
            float v1 = acc[mt][nt][1];
            float v2 = acc[mt][nt][2];
            float v3 = acc[mt][nt][3];
            if (MODE == 0) {
                const long long o0 = (long long)row * ldc + col;
                const long long o1 = o0 + 8LL * ldc;
                if (bias) {
                    float b0 = __ldg(bias + col), b1 = __ldg(bias + col + 1);
                    v0 += b0; v1 += b1; v2 += b0; v3 += b1;
                }
                if (Res) {
                    float2 r0 = *reinterpret_cast<const float2*>(Res + o0);
                    float2 r1 = *reinterpret_cast<const float2*>(Res + o1);
                    v0 += r0.x; v1 += r0.y; v2 += r1.x; v3 += r1.y;
                }
                *reinterpret_cast<float2*>(Cf + o0) = make_float2(v0, v1);
                *reinterpret_cast<float2*>(Cf + o1) = make_float2(v2, v3);
            } else {
                // cols interleaved: even col = gate_j, odd = up_j, j = col/2
                const int j = col >> 1;
                const long long o0 = (long long)row * ldc + j;
                const long long o1 = o0 + 8LL * ldc;
                float r0 = v0 / (1.f + expf(-v0)) * v1;
                float r2 = v2 / (1.f + expf(-v2)) * v3;
                bf16 h, l;
                split_bf16(r0, h, l); Chi[o0] = h; Clo[o0] = l;
                split_bf16(r2, h, l); Chi[o1] = h; Clo[o1] = l;
            }
        }
    }
}

// ---------------- flash attention (fused QK^T -> softmax -> PV) ----------------
// Pairing for causal balance: CTA p handles q-blocks [64p, 64p+64) (warps 0-3) and
// [960-64p, 1024-64p) (warps 4-7). Work = (17+p)+(32-p) = 49 tiles, constant.
#define TkF   64
#define QSTRB 272                   // Q/K smem row stride bytes (136 bf16)
#define VSTRB 144                   // V smem row stride bytes (72 bf16)
#define QPL   (128 * QSTRB)
#define KPL   (64 * QSTRB)
#define VPL   (128 * VSTRB)
#define FSTG  (2 * KPL + 2 * VPL)
#define FKOFF (2 * QPL)
#define FSMEM (FKOFF + 2 * FSTG)    // 212992

__global__ void __launch_bounds__(256, 1)
flash_kernel(const bf16* __restrict__ qhp, const bf16* __restrict__ qlp,
             const bf16* __restrict__ khp, const bf16* __restrict__ klp,
             const bf16* __restrict__ vthp, const bf16* __restrict__ vtlp,
             bf16* __restrict__ ohp, bf16* __restrict__ olp)
{
    extern __shared__ char smc[];
    const uint32_t smb = smem_u32(smc);
    const int tid = threadIdx.x, lane = tid & 31, wid = tid >> 5;
    const int pp = blockIdx.x, h = blockIdx.y;       // pair index 0..7
    const int baseA = 64 * pp;
    const int baseB = 960 - 64 * pp;
    const int kvh = h >> 3;
    const int nkt = 32 - pp;                          // group-B (max) tile count
    const int wg = wid >> 2;                          // 0 = block A, 1 = block B
    const int my_nkt = wg ? nkt : 17 + pp;            // group-A stops early

    // Q tile: smem rows 0-63 = block A, 64-127 = block B
    for (int c = tid; c < 2048; c += 256) {
        const int r = c >> 4, sg = c & 15;
        const int grow = (r < 64) ? (baseA + r) : (baseB + r - 64);
        const uint32_t d = smb + r * QSTRB + sg * 16;
        const size_t src = (size_t)grow * Hn + h * HDn + sg * 8;
        cpa16(d, qhp + src);
        cpa16(d + QPL, qlp + src);
    }
    cp_commit();

    auto load_kv = [&](int kt) {
        const int t0 = kt * TkF;
        const uint32_t base = smb + FKOFF + (kt & 1) * FSTG;
        for (int c = tid; c < 1024; c += 256) {
            const int r = c >> 4, sg = c & 15;
            const uint32_t d = base + r * QSTRB + sg * 16;
            const size_t src = ((size_t)kvh * Tn + t0 + r) * HDn + sg * 8;
            cpa16(d, khp + src);
            cpa16(d + KPL, klp + src);
        }
        for (int c = tid; c < 1024; c += 256) {
            const int r = c >> 3, sg = c & 7;
            const uint32_t d = base + 2 * KPL + r * VSTRB + sg * 16;
            const size_t src = ((size_t)kvh * HDn + r) * Tn + t0 + sg * 8;
            cpa16(d, vthp + src);
            cpa16(d + VPL, vtlp + src);
        }
    };
    load_kv(0); cp_commit();

    float O[16][4];
#pragma unroll
    for (int i = 0; i < 16; i++)
#pragma unroll
        for (int e = 0; e < 4; e++) O[i][e] = 0.f;
    float m1 = -1e30f, m2 = -1e30f, l1 = 0.f, l2 = 0.f;

    const int qrow1 = (wg ? baseB : baseA) + (wid & 3) * 16 + (lane >> 2);
    const int lim1 = Pn + qrow1;
    const int lim2 = lim1 + 8;

    const uint32_t qbase = smb +
        (wid * 16 + ((lane >> 3) & 1) * 8 + (lane & 7)) * QSTRB + ((lane >> 4) & 1) * 16;
    const uint32_t brow = ((lane >> 4) & 1) * 8 + (lane & 7);
    const uint32_t bcol = ((lane >> 3) & 1) * 16;

    for (int kt = 0; kt < nkt; kt++) {
        if (kt + 1 < nkt) { load_kv(kt + 1); cp_commit(); cp_wait1(); }
        else cp_wait0();
        __syncthreads();
        const uint32_t base = smb + FKOFF + (kt & 1) * FSTG;

        if (kt < my_nkt) {
            float S[8][4];
#pragma unroll
            for (int nt = 0; nt < 8; nt++)
#pragma unroll
                for (int e = 0; e < 4; e++) S[nt][e] = 0.f;
#pragma unroll
            for (int ks = 0; ks < 8; ks++) {
                uint32_t qa_h[4], qa_l[4];
                ldm4(qa_h, qbase + ks * 32);
                ldm4(qa_l, qbase + ks * 32 + QPL);
#pragma unroll
                for (int p = 0; p < 4; p++) {
                    uint32_t rh[4], rl[4];
                    const uint32_t a = base + (p * 16 + brow) * QSTRB + ks * 32 + bcol;
                    ldm4(rh, a);
                    ldm4(rl, a + KPL);
                    uint32_t bh0[2] = {rh[0], rh[1]}, bh1[2] = {rh[2], rh[3]};
                    uint32_t bl0[2] = {rl[0], rl[1]}, bl1[2] = {rl[2], rl[3]};
                    mma16816(S[2*p],   qa_h, bh0); mma16816(S[2*p],   qa_h, bl0); mma16816(S[2*p],   qa_l, bh0);
                    mma16816(S[2*p+1], qa_h, bh1); mma16816(S[2*p+1], qa_h, bl1); mma16816(S[2*p+1], qa_l, bh1);
                }
            }

            const int t0 = kt * TkF;
            float mx1 = -1e30f, mx2 = -1e30f;
#pragma unroll
            for (int nt = 0; nt < 8; nt++) {
                const int tb = t0 + nt * 8 + (lane & 3) * 2;
#pragma unroll
                for (int e = 0; e < 2; e++) {
                    S[nt][e]     = (tb + e <= lim1) ? S[nt][e]     * SCALEn : -1e30f;
                    S[nt][2 + e] = (tb + e <= lim2) ? S[nt][2 + e] * SCALEn : -1e30f;
                    mx1 = fmaxf(mx1, S[nt][e]);
                    mx2 = fmaxf(mx2, S[nt][2 + e]);
                }
            }
            mx1 = fmaxf(mx1, __shfl_xor_sync(~0u, mx1, 1));
            mx1 = fmaxf(mx1, __shfl_xor_sync(~0u, mx1, 2));
            mx2 = fmaxf(mx2, __shfl_xor_sync(~0u, mx2, 1));
            mx2 = fmaxf(mx2, __shfl_xor_sync(~0u, mx2, 2));
            const float mn1 = fmaxf(m1, mx1), mn2 = fmaxf(m2, mx2);
            const float sc1 = __expf(fmaxf(m1 - mn1, -80.f));
            const float sc2 = __expf(fmaxf(m2 - mn2, -80.f));
            m1 = mn1; m2 = mn2;
            float rs1 = 0.f, rs2 = 0.f;
#pragma unroll
            for (int nt = 0; nt < 8; nt++) {
                S[nt][0] = __expf(fmaxf(S[nt][0] - mn1, -80.f));
                S[nt][1] = __expf(fmaxf(S[nt][1] - mn1, -80.f));
                S[nt][2] = __expf(fmaxf(S[nt][2] - mn2, -80.f));
                S[nt][3] = __expf(fmaxf(S[nt][3] - mn2, -80.f));
                rs1 += S[nt][0] + S[nt][1];
                rs2 += S[nt][2] + S[nt][3];
            }
            rs1 += __shfl_xor_sync(~0u, rs1, 1); rs1 += __shfl_xor_sync(~0u, rs1, 2);
            rs2 += __shfl_xor_sync(~0u, rs2, 1); rs2 += __shfl_xor_sync(~0u, rs2, 2);
            l1 = l1 * sc1 + rs1;
            l2 = l2 * sc2 + rs2;
#pragma unroll
            for (int i = 0; i < 16; i++) {
                O[i][0] *= sc1; O[i][1] *= sc1; O[i][2] *= sc2; O[i][3] *= sc2;
            }

#pragma unroll
            for (int ks2 = 0; ks2 < 4; ks2++) {
                uint32_t pa_h[4], pa_l[4];
#pragma unroll
                for (int half = 0; half < 2; half++) {
                    const int nt = 2 * ks2 + half;
                    bf16 h0, g0, h1, g1, h2, g2, h3, g3;
                    split_bf16(S[nt][0], h0, g0); split_bf16(S[nt][1], h1, g1);
                    split_bf16(S[nt][2], h2, g2); split_bf16(S[nt][3], h3, g3);
                    pa_h[half ? 2 : 0] = b2u(__nv_bfloat162(h0, h1));
                    pa_h[half ? 3 : 1] = b2u(__nv_bfloat162(h2, h3));
                    pa_l[half ? 2 : 0] = b2u(__nv_bfloat162(g0, g1));
                    pa_l[half ? 3 : 1] = b2u(__nv_bfloat162(g2, g3));
                }
#pragma unroll
                for (int p2 = 0; p2 < 8; p2++) {
                    uint32_t rv[4], rvl[4];
                    const uint32_t a = base + 2 * KPL + (p2 * 16 + brow) * VSTRB + ks2 * 32 + bcol;
                    ldm4(rv, a);
                    ldm4(rvl, a + VPL);
                    uint32_t b0[2] = {rv[0], rv[1]},  b1[2] = {rv[2], rv[3]};
                    uint32_t c0[2] = {rvl[0], rvl[1]}, c1[2] = {rvl[2], rvl[3]};
                    mma16816(O[2*p2],   pa_h, b0); mma16816(O[2*p2],   pa_h, c0); mma16816(O[2*p2],   pa_l, b0);
                    mma16816(O[2*p2+1], pa_h, b1); mma16816(O[2*p2+1], pa_h, c1); mma16816(O[2*p2+1], pa_l, b1);
                }
            }
        }
        __syncthreads();
    }

    const float inv1 = 1.f / l1, inv2 = 1.f / l2;
    const int r1 = qrow1, r2 = qrow1 + 8;
    const int colb = h * HDn + (lane & 3) * 2;
#pragma unroll
    for (int nt2 = 0; nt2 < 16; nt2++) {
        const int col = colb + nt2 * 8;
        bf16 a0, b0, a1, b1;
        split_bf16(O[nt2][0] * inv1, a0, b0);
        split_bf16(O[nt2][1] * inv1, a1, b1);
        *reinterpret_cast<uint32_t*>(ohp + (size_t)r1 * Hn + col) = b2u(__nv_bfloat162(a0, a1));
        *reinterpret_cast<uint32_t*>(olp + (size_t)r1 * Hn + col) = b2u(__nv_bfloat162(b0, b1));
        split_bf16(O[nt2][2] * inv2, a0, b0);
        split_bf16(O[nt2][3] * inv2, a1, b1);
        *reinterpret_cast<uint32_t*>(ohp + (size_t)r2 * Hn + col) = b2u(__nv_bfloat162(a0, a1));
        *reinterpret_cast<uint32_t*>(olp + (size_t)r2 * Hn + col) = b2u(__nv_bfloat162(b0, b1));
    }
}

// ---------------- weight transpose + split: in[K,N] fp32 -> out[N*rmul+roff, K] bf16 hi/lo ----
struct __align__(16) B8 { bf16 v[8]; };

__global__ void __launch_bounds__(256)
convT_kernel(const float* __restrict__ in, bf16* __restrict__ hi, bf16* __restrict__ lo,
             int K, int N, int rmul, int roff)
{
    __shared__ float s[32][129];
    const int n0 = blockIdx.x * 128, k0 = blockIdx.y * 32;
    const int t = threadIdx.x;
    const int r = t >> 5, c4 = (t & 31) * 4;
    float4 v[4];
#pragma unroll
    for (int rr = 0; rr < 4; rr++)
        v[rr] = *reinterpret_cast<const float4*>(in + (size_t)(k0 + r + rr * 8) * N + n0 + c4);
#pragma unroll
    for (int rr = 0; rr < 4; rr++) {
        const int k = r + rr * 8;
        s[k][c4] = v[rr].x; s[k][c4+1] = v[rr].y; s[k][c4+2] = v[rr].z; s[k][c4+3] = v[rr].w;
    }
    __syncthreads();
    const int n = t >> 1, kk0 = (t & 1) * 16;
    B8 hb[2], lb[2];
#pragma unroll
    for (int kk = 0; kk < 16; kk++) {
        bf16 h, l;
        split_bf16(s[kk0 + kk][n], h, l);
        hb[kk >> 3].v[kk & 7] = h;
        lb[kk >> 3].v[kk & 7] = l;
    }
    const size_t o = (size_t)((n0 + n) * rmul + roff) * K + k0 + kk0;
    *reinterpret_cast<B8*>(hi + o)     = hb[0];
    *reinterpret_cast<B8*>(hi + o + 8) = hb[1];
    *reinterpret_cast<B8*>(lo + o)     = lb[0];
    *reinterpret_cast<B8*>(lo + o + 8) = lb[1];
}

// ---------------- pack QKV biases into one 2560-vector ----------------
__global__ void packbias_kernel(const float* __restrict__ bq, const float* __restrict__ bk,
                                const float* __restrict__ bv, float* __restrict__ o)
{
    int i = blockIdx.x * 256 + threadIdx.x;
    if (i < 2048) o[i] = bq[i];
    else if (i < 2304) o[i] = bk[i - 2048];
    else if (i < 2560) o[i] = bv[i - 2304];
}

// ---------------- RMSNorm: MODE 0 -> fp32 out, MODE 1 -> bf16 hi/lo ----------------
template<int MODE>
__global__ void __launch_bounds__(256)
rmsnorm_kernel(const float* __restrict__ x, const float* __restrict__ w,
               float* __restrict__ yf, bf16* __restrict__ yh, bf16* __restrict__ yl)
{
    int s = blockIdx.x;
    const float* row = x + (size_t)s * Hn;
    float4 buf[2];
    float ss = 0.f;
#pragma unroll
    for (int it = 0; it < 2; it++) {
        int j = (it * 256 + threadIdx.x) * 4;
        float4 v = *reinterpret_cast<const float4*>(row + j);
        buf[it] = v;
        ss += v.x * v.x + v.y * v.y + v.z * v.z + v.w * v.w;
    }
    ss = blockSum256(ss);
    float inv = rsqrtf(ss * (1.0f / Hn) + EPSn);
#pragma unroll
    for (int it = 0; it < 2; it++) {
        int j = (it * 256 + threadIdx.x) * 4;
        float4 wv = *reinterpret_cast<const float4*>(w + j);
        float o0 = buf[it].x * inv * wv.x;
        float o1 = buf[it].y * inv * wv.y;
        float o2 = buf[it].z * inv * wv.z;
        float o3 = buf[it].w * inv * wv.w;
        if (MODE == 0) {
            *reinterpret_cast<float4*>(yf + (size_t)s * Hn + j) = make_float4(o0, o1, o2, o3);
        } else {
            bf16 h0,l0,h1,l1,h2,l2,h3,l3;
            split_bf16(o0,h0,l0); split_bf16(o1,h1,l1);
            split_bf16(o2,h2,l2); split_bf16(o3,h3,l3);
            __nv_bfloat162 hh0(h0,h1), hh1(h2,h3), ll0(l0,l1), ll1(l2,l3);
            uint2 uh = make_uint2(b2u(hh0), b2u(hh1));
            uint2 ul = make_uint2(b2u(ll0), b2u(ll1));
            *reinterpret_cast<uint2*>(yh + (size_t)s * Hn + j) = uh;
            *reinterpret_cast<uint2*>(yl + (size_t)s * Hn + j) = ul;
        }
    }
}

// ---------------- RoPE for Q: fp32 (strided in qkv) -> bf16 hi/lo dense [S,2048] ----------------
__global__ void rope_q_kernel(const float* __restrict__ qkv, const int* __restrict__ pos,
                              bf16* __restrict__ qh, bf16* __restrict__ ql)
{
    int s = blockIdx.x, h = blockIdx.y, d = threadIdx.x; // d in [0,64)
    double ang = (double)pos[s] * exp(-(double)d / 64.0 * 13.815510557964274);
    double sd, cd; sincos(ang, &sd, &cd);
    float c = (float)cd, sn = (float)sd;
    size_t ibase = (size_t)s * 2560 + h * HDn;
    size_t obase = ((size_t)s * NHn + h) * HDn;
    float x1 = qkv[ibase + d], x2 = qkv[ibase + d + 64];
    float v1 = x1 * c - x2 * sn;
    float v2 = x2 * c + x1 * sn;
    bf16 hh, ll;
    split_bf16(v1, hh, ll); qh[obase + d] = hh;      ql[obase + d] = ll;
    split_bf16(v2, hh, ll); qh[obase + d + 64] = hh; ql[obase + d + 64] = ll;
}

// ---------------- K/V cache: tiled 32t x 128d; coalesced transposed V via smem ----------------
__global__ void __launch_bounds__(256)
kv_cache_kernel(const float* __restrict__ qkv,
                const float* __restrict__ pastk, const float* __restrict__ pastv,
                const int* __restrict__ pos,
                float* __restrict__ kc, float* __restrict__ vc,
                bf16* __restrict__ kh, bf16* __restrict__ kl,
                bf16* __restrict__ vth, bf16* __restrict__ vtl)
{
    __shared__ float sv[32][129];
    const int t0 = blockIdx.x * 32, kv = blockIdx.y;
    const int tid = threadIdx.x;

#pragma unroll
    for (int i = 0; i < 16; i++) {
        const int idx = i * 256 + tid;          // 0..4095
        const int tt = idx >> 7, d = idx & 127;
        const int t = t0 + tt;
        float kval, vval;
        if (t < Pn) {
            size_t pidx = ((size_t)kv * Pn + t) * HDn + d;
            kval = pastk[pidx];
            vval = pastv[pidx];
        } else {
            int s = t - Pn;
            const float* kr = qkv + (size_t)s * 2560 + 2048 + kv * HDn;
            int dr = d & 63;
            double ang = (double)pos[s] * exp(-(double)dr / 64.0 * 13.815510557964274);
            double sd, cd; sincos(ang, &sd, &cd);
            float c = (float)cd, sn = (float)sd;
            if (d < 64) kval = kr[d] * c - kr[d + 64] * sn;
            else        kval = kr[d] * c + kr[d - 64] * sn;
            vval = qkv[(size_t)s * 2560 + 2304 + kv * HDn + d];
        }
        size_t oidx = ((size_t)kv * Tn + t) * HDn + d;
        kc[oidx] = kval;
        vc[oidx] = vval;
        bf16 h, l;
        split_bf16(kval, h, l);
        kh[oidx] = h; kl[oidx] = l;
        sv[tt][d] = vval;
    }
    __syncthreads();

    const int tt = tid & 31, dw = tid >> 5;
#pragma unroll
    for (int d0 = 0; d0 < 128; d0 += 8) {
        const int d = d0 + dw;
        bf16 h, l;
        split_bf16(sv[tt][d], h, l);
        size_t o = ((size_t)kv * HDn + d) * Tn + t0 + tt;
        vth[o] = h; vtl[o] = l;
    }
}

// ---------------- host-side launch helpers ----------------
static void mmagemm(const bf16* Ah, const bf16* Al, const bf16* Bh, const bf16* Bl,
                    const float* bias, const float* Res, float* Cf,
                    int M, int N, int K, int lda, int ldb, int ldc)
{
    dim3 grid(N / 128, M / 128, 1);
    mma_gemm<0><<<grid, 256, NSTAGE * STAGEB>>>(Ah, Al, Bh, Bl, bias, Res, Cf,
                                                nullptr, nullptr, K, lda, ldb, ldc);
}
static void mmagemm_gu(const bf16* Ah, const bf16* Al, const bf16* Bh, const bf16* Bl,
                       bf16* Chi, bf16* Clo, int M, int N, int K, int lda, int ldb, int ldc)
{
    dim3 grid(N / 128, M / 128, 1);
    mma_gemm<1><<<grid, 256, NSTAGE * STAGEB>>>(Ah, Al, Bh, Bl, nullptr, nullptr, nullptr,
                                                Chi, Clo, K, lda, ldb, ldc);
}

extern "C" void kernel_launch(void* const* d_in, const int* in_sizes, int n_in,
                              void* d_out, int out_size)
{
    (void)in_sizes; (void)n_in; (void)out_size;
    const float* embeds = (const float*)d_in[0];
    const int*   pos    = (const int*)  d_in[1];
    const float* past_k = (const float*)d_in[2];
    const float* past_v = (const float*)d_in[3];
    const float* ln1    = (const float*)d_in[4];
    const float* wq     = (const float*)d_in[5];
    const float* bq     = (const float*)d_in[6];
    const float* wk     = (const float*)d_in[7];
    const float* bk     = (const float*)d_in[8];
    const float* wv     = (const float*)d_in[9];
    const float* bv     = (const float*)d_in[10];
    const float* wo     = (const float*)d_in[11];
    const float* ln2    = (const float*)d_in[12];
    const float* wg     = (const float*)d_in[13];
    const float* wu     = (const float*)d_in[14];
    const float* wd     = (const float*)d_in[15];
    const float* normw  = (const float*)d_in[16];
    float* out = (float*)d_out;

    cudaFuncSetAttribute(mma_gemm<0>, cudaFuncAttributeMaxDynamicSharedMemorySize, NSTAGE * STAGEB);
    cudaFuncSetAttribute(mma_gemm<1>, cudaFuncAttributeMaxDynamicSharedMemorySize, NSTAGE * STAGEB);
    cudaFuncSetAttribute(flash_kernel, cudaFuncAttributeMaxDynamicSharedMemorySize, FSMEM);

    float *hid, *qkv, *bqkv;
    cudaGetSymbolAddress((void**)&hid,  g_hid);
    cudaGetSymbolAddress((void**)&qkv,  g_qkv);
    cudaGetSymbolAddress((void**)&bqkv, g_bqkv);
    bf16 *hnh,*hnl,*qh,*ql,*kh,*kl,*vth,*vtl,*ath,*atl,*gh,*gl,*wh,*wl;
    cudaGetSymbolAddress((void**)&hnh, g_hn_hi); cudaGetSymbolAddress((void**)&hnl, g_hn_lo);
    cudaGetSymbolAddress((void**)&qh,  g_q_hi);  cudaGetSymbolAddress((void**)&ql,  g_q_lo);
    cudaGetSymbolAddress((void**)&kh,  g_k_hi);  cudaGetSymbolAddress((void**)&kl,  g_k_lo);
    cudaGetSymbolAddress((void**)&vth, g_vt_hi); cudaGetSymbolAddress((void**)&vtl, g_vt_lo);
    cudaGetSymbolAddress((void**)&ath, g_at_hi); cudaGetSymbolAddress((void**)&atl, g_at_lo);
    cudaGetSymbolAddress((void**)&gh,  g_g_hi);  cudaGetSymbolAddress((void**)&gl,  g_g_lo);
    cudaGetSymbolAddress((void**)&wh,  g_w_hi);  cudaGetSymbolAddress((void**)&wl,  g_w_lo);

    // per-layer offsets into transposed weight store
    // [OQ: qkv 2560 rows][OO: wo 2048 rows][OG: gate/up interleaved 11264 rows][OD: wd 2048 rows]
    const long long OQ = 0, OO = 5242880, OG = 9437184, OD = 32505856;
    const long long OK_ = 4194304, OV = 4718592;

    // ---- second stream for weight-conversion overlap (leaked; few calls total) ----
    cudaStream_t s2;
    cudaStreamCreateWithFlags(&s2, cudaStreamNonBlocking);
    cudaEvent_t evFork, evJoin;
    cudaEventCreateWithFlags(&evFork, cudaEventDisableTiming);
    cudaEventCreateWithFlags(&evJoin, cudaEventDisableTiming);

    dim3 cb(256);
    // fork: s2 depends only on capture start
    cudaEventRecord(evFork, 0);
    cudaStreamWaitEvent(s2, evFork, 0);

    // critical-path convT (layer 0 QKV weights) on stream 0
    {
        long long base = 0;
        convT_kernel<<<dim3(2048/128, 2048/32), cb>>>(wq, wh + base + OQ,  wl + base + OQ,  Hn, 2048, 1, 0);
        convT_kernel<<<dim3(256/128,  2048/32), cb>>>(wk, wh + base + OK_, wl + base + OK_, Hn, 256, 1, 0);
        convT_kernel<<<dim3(256/128,  2048/32), cb>>>(wv, wh + base + OV,  wl + base + OV,  Hn, 256, 1, 0);
    }
    // all remaining convT on s2 (overlaps layer-0 front)
    {
        long long b0 = 0;
        convT_kernel<<<dim3(2048/128, 2048/32), cb, 0, s2>>>(wo, wh + b0 + OO, wl + b0 + OO, Hn, 2048, 1, 0);
        convT_kernel<<<dim3(5632/128, 2048/32), cb, 0, s2>>>(wg, wh + b0 + OG, wl + b0 + OG, Hn, FFn, 2, 0);
        convT_kernel<<<dim3(5632/128, 2048/32), cb, 0, s2>>>(wu, wh + b0 + OG, wl + b0 + OG, Hn, FFn, 2, 1);
        convT_kernel<<<dim3(2048/128, 5632/32), cb, 0, s2>>>(wd, wh + b0 + OD, wl + b0 + OD, FFn, 2048, 1, 0);
        long long b1 = WL;
        convT_kernel<<<dim3(2048/128, 2048/32), cb, 0, s2>>>(wq + (size_t)Hn*2048, wh + b1 + OQ,  wl + b1 + OQ,  Hn, 2048, 1, 0);
        convT_kernel<<<dim3(256/128,  2048/32), cb, 0, s2>>>(wk + (size_t)Hn*256,  wh + b1 + OK_, wl + b1 + OK_, Hn, 256, 1, 0);
        convT_kernel<<<dim3(256/128,  2048/32), cb, 0, s2>>>(wv + (size_t)Hn*256,  wh + b1 + OV,  wl + b1 + OV,  Hn, 256, 1, 0);
        convT_kernel<<<dim3(2048/128, 2048/32), cb, 0, s2>>>(wo + (size_t)Hn*Hn,   wh + b1 + OO,  wl + b1 + OO,  Hn, 2048, 1, 0);
        convT_kernel<<<dim3(5632/128, 2048/32), cb, 0, s2>>>(wg + (size_t)Hn*FFn,  wh + b1 + OG,  wl + b1 + OG,  Hn, FFn, 2, 0);
        convT_kernel<<<dim3(5632/128, 2048/32), cb, 0, s2>>>(wu + (size_t)Hn*FFn,  wh + b1 + OG,  wl + b1 + OG,  Hn, FFn, 2, 1);
        convT_kernel<<<dim3(2048/128, 5632/32), cb, 0, s2>>>(wd + (size_t)FFn*Hn,  wh + b1 + OD,  wl + b1 + OD,  FFn, 2048, 1, 0);
        cudaEventRecord(evJoin, s2);
    }

    cudaMemcpyAsync(hid, embeds, sizeof(float) * Sn * Hn, cudaMemcpyDeviceToDevice);

    bool joined = false;
    for (int l = 0; l < Ln; l++) {
        long long base = (long long)l * WL;
        float* kc = out + (size_t)Sn * Hn + (size_t)l * 2 * NKVn * Tn * HDn;
        float* vc = kc + (size_t)NKVn * Tn * HDn;

        // pre-attention norm -> bf16 hi/lo
        rmsnorm_kernel<1><<<Sn, 256>>>(hid, ln1 + (size_t)l * Hn, nullptr, hnh, hnl);

        // fused QKV projection (N=2560) -> fp32 qkv buffer
        packbias_kernel<<<10, 256>>>(bq + (size_t)l*2048, bk + (size_t)l*256, bv + (size_t)l*256, bqkv);
        mmagemm(hnh, hnl, wh + base + OQ, wl + base + OQ, bqkv, nullptr,
                qkv, Sn, 2560, Hn, Hn, Hn, 2560);

        // RoPE Q -> bf16 hi/lo; KV cache (fp32 to d_out + bf16 hi/lo, V transposed)
        rope_q_kernel<<<dim3(Sn, NHn), 64>>>(qkv, pos, qh, ql);
        kv_cache_kernel<<<dim3(Tn / 32, NKVn), 256>>>(
            qkv,
            past_k + (size_t)l * NKVn * Pn * HDn,
            past_v + (size_t)l * NKVn * Pn * HDn,
            pos, kc, vc, kh, kl, vth, vtl);

        // fused attention (paired causal blocks): QK^T -> online softmax -> PV
        flash_kernel<<<dim3(8, NHn), 256, FSMEM>>>(qh, ql, kh, kl, vth, vtl, ath, atl);

        // join s2 before first use of non-QKV weights
        if (!joined) { cudaStreamWaitEvent(0, evJoin, 0); joined = true; }

        // output projection + residual (fp32)
        mmagemm(ath, atl, wh + base + OO, wl + base + OO, nullptr, hid,
                hid, Sn, Hn, Hn, Hn, Hn, Hn);

        // MLP: gate|up interleaved GEMM with fused SiLU epilogue -> bf16 hi/lo, then down
        rmsnorm_kernel<1><<<Sn, 256>>>(hid, ln2 + (size_t)l * Hn, nullptr, hnh, hnl);
        mmagemm_gu(hnh, hnl, wh + base + OG, wl + base + OG, gh, gl,
                   Sn, 2*FFn, Hn, Hn, Hn, FFn);
        mmagemm(gh, gl, wh + base + OD, wl + base + OD, nullptr, hid,
                hid, Sn, Hn, FFn, FFn, FFn, Hn);
    }

    // final norm -> fp32 hidden output
    rmsnorm_kernel<0><<<Sn, 256>>>(hid, normw, out, nullptr, nullptr);
}

// round 17
// speedup vs baseline: 1.2016x; 1.0852x over previous
#include <cuda_runtime.h>
#include <cuda_bf16.h>
#include <math.h>
#include <stdint.h>

// ---------------- problem constants ----------------
#define Ln   2
#define Hn   2048
#define NHn  16
#define NKVn 2
#define HDn  128
#define Sn   1024
#define Pn   1024
#define FFn  5632
#define Tn   (Pn + Sn)       // 2048
#define Gn   (NHn / NKVn)    // 8
#define EPSn 1e-6f
#define SCALEn 0.08838834764831845f  // 1/sqrt(128)

typedef __nv_bfloat16 bf16;

// ---------------- device scratch (static, no allocation) ----------------
static __device__ float g_hid   [Sn * Hn];
static __device__ float g_qkv   [Sn * 2560];
static __device__ float g_bqkv  [2560];

static __device__ bf16 g_hn_hi[Sn * Hn],  g_hn_lo[Sn * Hn];
static __device__ bf16 g_q_hi [Sn * Hn],  g_q_lo [Sn * Hn];
static __device__ bf16 g_k_hi [NKVn * Tn * HDn], g_k_lo [NKVn * Tn * HDn];
static __device__ bf16 g_vt_hi[NKVn * HDn * Tn], g_vt_lo[NKVn * HDn * Tn];
static __device__ bf16 g_at_hi[Sn * Hn],  g_at_lo[Sn * Hn];
static __device__ bf16 g_g_hi [(size_t)Sn * FFn], g_g_lo [(size_t)Sn * FFn];

// transposed+split weights: per layer [wq(2048x2048), wk(256x2048), wv(256x2048),
//  wo(2048x2048), gu_interleaved(11264x2048), wd(2048x5632)]  (all [N,K])
#define WL 44040192LL
#define WTOT (2 * WL)
static __device__ bf16 g_w_hi[WTOT], g_w_lo[WTOT];

// ---------------- small helpers ----------------
__device__ __forceinline__ float warpSum(float v) {
#pragma unroll
    for (int o = 16; o; o >>= 1) v += __shfl_xor_sync(0xffffffffu, v, o);
    return v;
}
__device__ float blockSum256(float v) {
    __shared__ float sm[8]; __shared__ float res;
    v = warpSum(v);
    if ((threadIdx.x & 31) == 0) sm[threadIdx.x >> 5] = v;
    __syncthreads();
    float w = (threadIdx.x < 8) ? sm[threadIdx.x] : 0.f;
    w = warpSum(w);
    if (threadIdx.x == 0) res = w;
    __syncthreads();
    return res;
}

__device__ __forceinline__ void split_bf16(float x, bf16& h, bf16& l) {
    h = __float2bfloat16(x);
    l = __float2bfloat16(x - __bfloat162float(h));
}
__device__ __forceinline__ uint32_t b2u(__nv_bfloat162 v) {
    return *reinterpret_cast<uint32_t*>(&v);
}

// ---------------- PTX wrappers (plain sm_80+ features only) ----------------
__device__ __forceinline__ uint32_t smem_u32(const void* p) {
    uint32_t a;
    asm("{ .reg .u64 t; cvta.to.shared.u64 t, %1; cvt.u32.u64 %0, t; }" : "=r"(a) : "l"(p));
    return a;
}
__device__ __forceinline__ void cpa16(uint32_t d, const void* s) {
    asm volatile("cp.async.cg.shared.global [%0], [%1], 16;" :: "r"(d), "l"(s));
}
__device__ __forceinline__ void cp_commit() {
    asm volatile("cp.async.commit_group;" ::: "memory");
}
__device__ __forceinline__ void cp_wait1() {
    asm volatile("cp.async.wait_group 1;" ::: "memory");
}
__device__ __forceinline__ void cp_wait0() {
    asm volatile("cp.async.wait_group 0;" ::: "memory");
}
__device__ __forceinline__ void ldm4(uint32_t* r, uint32_t a) {
    asm volatile("ldmatrix.sync.aligned.m8n8.x4.shared.b16 {%0,%1,%2,%3}, [%4];"
        : "=r"(r[0]), "=r"(r[1]), "=r"(r[2]), "=r"(r[3]) : "r"(a));
}
__device__ __forceinline__ void mma16816(float* c, const uint32_t* a, const uint32_t* b) {
    asm volatile(
        "mma.sync.aligned.m16n8k16.row.col.f32.bf16.bf16.f32 "
        "{%0,%1,%2,%3}, {%4,%5,%6,%7}, {%8,%9}, {%0,%1,%2,%3};"
        : "+f"(c[0]), "+f"(c[1]), "+f"(c[2]), "+f"(c[3])
        : "r"(a[0]), "r"(a[1]), "r"(a[2]), "r"(a[3]), "r"(b[0]), "r"(b[1]));
}

// ---------------- tensor-core GEMM (mma.sync bf16, 3-way split, 2-stage pipe, 2 CTA/SM) ----
// C[M,N] = A[M,K] @ B[N,K]^T. A/B are bf16 hi/lo pairs.
// MODE 0: fp32 out (+bias)(+Res).  MODE 1: gate/up interleaved cols -> silu(g)*u, bf16 hi/lo
//         out at [row, col/2] with row stride ldc.
#define AST  40                        // smem row stride in bf16 (80 B)
#define TILEB (128 * AST * 2)          // 10240 B per plane
#define STAGEB (4 * TILEB)             // Ah, Al, Bh, Bl
#define NSTAGE 2

template<int MODE>
__global__ void __launch_bounds__(256, 2)
mma_gemm(const bf16* __restrict__ Ah, const bf16* __restrict__ Al,
         const bf16* __restrict__ Bh, const bf16* __restrict__ Bl,
         const float* __restrict__ bias, const float* __restrict__ Res,
         float* __restrict__ Cf, bf16* __restrict__ Chi, bf16* __restrict__ Clo,
         int K, int lda, int ldb, int ldc)
{
    extern __shared__ char smc[];
    const int tid = threadIdx.x;
    const int lane = tid & 31;
    const int wid = tid >> 5;
    const int wm = wid >> 2;           // 0..1
    const int wn = wid & 3;            // 0..3
    const int row0 = blockIdx.y * 128;
    const int col0 = blockIdx.x * 128;

    const uint32_t smb = smem_u32(smc);

    float acc[4][4][4];
#pragma unroll
    for (int i = 0; i < 4; i++)
#pragma unroll
        for (int j = 0; j < 4; j++)
#pragma unroll
            for (int e = 0; e < 4; e++) acc[i][j][e] = 0.f;

    const int nk = K >> 5;

    auto load_tile = [&](int i) {
        const int k0 = i << 5;
        const uint32_t sb = smb + (i & 1) * STAGEB;
#pragma unroll
        for (int c = tid; c < 512; c += 256) {
            const int r = c >> 2, sg = c & 3;
            const uint32_t d = sb + r * (AST * 2) + sg * 16;
            const size_t ga = (size_t)(row0 + r) * lda + k0 + sg * 8;
            const size_t gb = (size_t)(col0 + r) * ldb + k0 + sg * 8;
            cpa16(d,             Ah + ga);
            cpa16(d + TILEB,     Al + ga);
            cpa16(d + 2 * TILEB, Bh + gb);
            cpa16(d + 3 * TILEB, Bl + gb);
        }
    };

    load_tile(0); cp_commit();

    for (int i = 0; i < nk; i++) {
        if (i + 1 < nk) { load_tile(i + 1); cp_commit(); cp_wait1(); }
        else cp_wait0();
        __syncthreads();

        const uint32_t sb = smb + (i & 1) * STAGEB;
#pragma unroll
        for (int ks = 0; ks < 2; ks++) {
            uint32_t ah[4][4], al[4][4], bh[4][2], bl[4][2];
            const int acol = ks * 32 + ((lane >> 4) & 1) * 16;
#pragma unroll
            for (int mt = 0; mt < 4; mt++) {
                const int row = wm * 64 + mt * 16 + ((lane >> 3) & 1) * 8 + (lane & 7);
                const uint32_t a = sb + row * (AST * 2) + acol;
                ldm4(ah[mt], a);
                ldm4(al[mt], a + TILEB);
            }
            const int bcol = ks * 32 + ((lane >> 3) & 1) * 16;
#pragma unroll
            for (int p = 0; p < 2; p++) {
                const int row = wn * 32 + p * 16 + ((lane >> 4) & 1) * 8 + (lane & 7);
                const uint32_t a = sb + 2 * TILEB + row * (AST * 2) + bcol;
                uint32_t r[4];
                ldm4(r, a);
                bh[2*p][0] = r[0]; bh[2*p][1] = r[1];
                bh[2*p+1][0] = r[2]; bh[2*p+1][1] = r[3];
                ldm4(r, a + TILEB);
                bl[2*p][0] = r[0]; bl[2*p][1] = r[1];
                bl[2*p+1][0] = r[2]; bl[2*p+1][1] = r[3];
            }
#pragma unroll
            for (int mt = 0; mt < 4; mt++)
#pragma unroll
                for (int nt = 0; nt < 4; nt++) {
                    mma16816(acc[mt][nt], ah[mt], bh[nt]);
                    mma16816(acc[mt][nt], ah[mt], bl[nt]);
                    mma16816(acc[mt][nt], al[mt], bh[nt]);
                }
        }
        __syncthreads();
    }

#pragma unroll
    for (int mt = 0; mt < 4; mt++) {
#pragma unroll
        for (int nt = 0; nt < 4; nt++) {
            const int row = row0 + wm * 64 + mt * 16 + (lane >> 2);
            const int col = col0 + wn * 32 + nt * 8 + (lane & 3) * 2;
            float v0 = acc[mt][nt][0];
            float v1 = acc[mt][nt][1];
            float v2 = acc[mt][nt][2];
            float v3 = acc[mt][nt][3];
            if (MODE == 0) {
                const long long o0 = (long long)row * ldc + col;
                const long long o1 = o0 + 8LL * ldc;
                if (bias) {
                    float b0 = __ldg(bias + col), b1 = __ldg(bias + col + 1);
                    v0 += b0; v1 += b1; v2 += b0; v3 += b1;
                }
                if (Res) {
                    float2 r0 = *reinterpret_cast<const float2*>(Res + o0);
                    float2 r1 = *reinterpret_cast<const float2*>(Res + o1);
                    v0 += r0.x; v1 += r0.y; v2 += r1.x; v3 += r1.y;
                }
                *reinterpret_cast<float2*>(Cf + o0) = make_float2(v0, v1);
                *reinterpret_cast<float2*>(Cf + o1) = make_float2(v2, v3);
            } else {
                // cols interleaved: even col = gate_j, odd = up_j, j = col/2
                const int j = col >> 1;
                const long long o0 = (long long)row * ldc + j;
                const long long o1 = o0 + 8LL * ldc;
                float r0 = v0 / (1.f + expf(-v0)) * v1;
                float r2 = v2 / (1.f + expf(-v2)) * v3;
                bf16 h, l;
                split_bf16(r0, h, l); Chi[o0] = h; Clo[o0] = l;
                split_bf16(r2, h, l); Chi[o1] = h; Clo[o1] = l;
            }
        }
    }
}

// ---------------- flash attention (fused QK^T -> softmax -> PV) ----------------
// Pairing for causal balance: CTA p handles q-blocks [64p, 64p+64) (warps 0-3) and
// [960-64p, 1024-64p) (warps 4-7). Work = (17+p)+(32-p) = 49 tiles, constant.
#define TkF   64
#define QSTRB 272                   // Q/K smem row stride bytes (136 bf16)
#define VSTRB 144                   // V smem row stride bytes (72 bf16)
#define QPL   (128 * QSTRB)
#define KPL   (64 * QSTRB)
#define VPL   (128 * VSTRB)
#define FSTG  (2 * KPL + 2 * VPL)
#define FKOFF (2 * QPL)
#define FSMEM (FKOFF + 2 * FSTG)    // 212992

__global__ void __launch_bounds__(256, 1)
flash_kernel(const bf16* __restrict__ qhp, const bf16* __restrict__ qlp,
             const bf16* __restrict__ khp, const bf16* __restrict__ klp,
             const bf16* __restrict__ vthp, const bf16* __restrict__ vtlp,
             bf16* __restrict__ ohp, bf16* __restrict__ olp)
{
    extern __shared__ char smc[];
    const uint32_t smb = smem_u32(smc);
    const int tid = threadIdx.x, lane = tid & 31, wid = tid >> 5;
    const int pp = blockIdx.x, h = blockIdx.y;       // pair index 0..7
    const int baseA = 64 * pp;
    const int baseB = 960 - 64 * pp;
    const int kvh = h >> 3;
    const int nkt = 32 - pp;                          // group-B (max) tile count
    const int wg = wid >> 2;                          // 0 = block A, 1 = block B
    const int my_nkt = wg ? nkt : 17 + pp;            // group-A stops early

    // Q tile: smem rows 0-63 = block A, 64-127 = block B
    for (int c = tid; c < 2048; c += 256) {
        const int r = c >> 4, sg = c & 15;
        const int grow = (r < 64) ? (baseA + r) : (baseB + r - 64);
        const uint32_t d = smb + r * QSTRB + sg * 16;
        const size_t src = (size_t)grow * Hn + h * HDn + sg * 8;
        cpa16(d, qhp + src);
        cpa16(d + QPL, qlp + src);
    }
    cp_commit();

    auto load_kv = [&](int kt) {
        const int t0 = kt * TkF;
        const uint32_t base = smb + FKOFF + (kt & 1) * FSTG;
        for (int c = tid; c < 1024; c += 256) {
            const int r = c >> 4, sg = c & 15;
            const uint32_t d = base + r * QSTRB + sg * 16;
            const size_t src = ((size_t)kvh * Tn + t0 + r) * HDn + sg * 8;
            cpa16(d, khp + src);
            cpa16(d + KPL, klp + src);
        }
        for (int c = tid; c < 1024; c += 256) {
            const int r = c >> 3, sg = c & 7;
            const uint32_t d = base + 2 * KPL + r * VSTRB + sg * 16;
            const size_t src = ((size_t)kvh * HDn + r) * Tn + t0 + sg * 8;
            cpa16(d, vthp + src);
            cpa16(d + VPL, vtlp + src);
        }
    };
    load_kv(0); cp_commit();

    float O[16][4];
#pragma unroll
    for (int i = 0; i < 16; i++)
#pragma unroll
        for (int e = 0; e < 4; e++) O[i][e] = 0.f;
    float m1 = -1e30f, m2 = -1e30f, l1 = 0.f, l2 = 0.f;

    const int qrow1 = (wg ? baseB : baseA) + (wid & 3) * 16 + (lane >> 2);
    const int lim1 = Pn + qrow1;
    const int lim2 = lim1 + 8;

    const uint32_t qbase = smb +
        (wid * 16 + ((lane >> 3) & 1) * 8 + (lane & 7)) * QSTRB + ((lane >> 4) & 1) * 16;
    const uint32_t brow = ((lane >> 4) & 1) * 8 + (lane & 7);
    const uint32_t bcol = ((lane >> 3) & 1) * 16;

    for (int kt = 0; kt < nkt; kt++) {
        if (kt + 1 < nkt) { load_kv(kt + 1); cp_commit(); cp_wait1(); }
        else cp_wait0();
        __syncthreads();
        const uint32_t base = smb + FKOFF + (kt & 1) * FSTG;

        if (kt < my_nkt) {
            float S[8][4];
#pragma unroll
            for (int nt = 0; nt < 8; nt++)
#pragma unroll
                for (int e = 0; e < 4; e++) S[nt][e] = 0.f;
#pragma unroll
            for (int ks = 0; ks < 8; ks++) {
                uint32_t qa_h[4], qa_l[4];
                ldm4(qa_h, qbase + ks * 32);
                ldm4(qa_l, qbase + ks * 32 + QPL);
#pragma unroll
                for (int p = 0; p < 4; p++) {
                    uint32_t rh[4], rl[4];
                    const uint32_t a = base + (p * 16 + brow) * QSTRB + ks * 32 + bcol;
                    ldm4(rh, a);
                    ldm4(rl, a + KPL);
                    uint32_t bh0[2] = {rh[0], rh[1]}, bh1[2] = {rh[2], rh[3]};
                    uint32_t bl0[2] = {rl[0], rl[1]}, bl1[2] = {rl[2], rl[3]};
                    mma16816(S[2*p],   qa_h, bh0); mma16816(S[2*p],   qa_h, bl0); mma16816(S[2*p],   qa_l, bh0);
                    mma16816(S[2*p+1], qa_h, bh1); mma16816(S[2*p+1], qa_h, bl1); mma16816(S[2*p+1], qa_l, bh1);
                }
            }

            const int t0 = kt * TkF;
            float mx1 = -1e30f, mx2 = -1e30f;
#pragma unroll
            for (int nt = 0; nt < 8; nt++) {
                const int tb = t0 + nt * 8 + (lane & 3) * 2;
#pragma unroll
                for (int e = 0; e < 2; e++) {
                    S[nt][e]     = (tb + e <= lim1) ? S[nt][e]     * SCALEn : -1e30f;
                    S[nt][2 + e] = (tb + e <= lim2) ? S[nt][2 + e] * SCALEn : -1e30f;
                    mx1 = fmaxf(mx1, S[nt][e]);
                    mx2 = fmaxf(mx2, S[nt][2 + e]);
                }
            }
            mx1 = fmaxf(mx1, __shfl_xor_sync(~0u, mx1, 1));
            mx1 = fmaxf(mx1, __shfl_xor_sync(~0u, mx1, 2));
            mx2 = fmaxf(mx2, __shfl_xor_sync(~0u, mx2, 1));
            mx2 = fmaxf(mx2, __shfl_xor_sync(~0u, mx2, 2));
            const float mn1 = fmaxf(m1, mx1), mn2 = fmaxf(m2, mx2);
            const float sc1 = __expf(fmaxf(m1 - mn1, -80.f));
            const float sc2 = __expf(fmaxf(m2 - mn2, -80.f));
            m1 = mn1; m2 = mn2;
            float rs1 = 0.f, rs2 = 0.f;
#pragma unroll
            for (int nt = 0; nt < 8; nt++) {
                S[nt][0] = __expf(fmaxf(S[nt][0] - mn1, -80.f));
                S[nt][1] = __expf(fmaxf(S[nt][1] - mn1, -80.f));
                S[nt][2] = __expf(fmaxf(S[nt][2] - mn2, -80.f));
                S[nt][3] = __expf(fmaxf(S[nt][3] - mn2, -80.f));
                rs1 += S[nt][0] + S[nt][1];
                rs2 += S[nt][2] + S[nt][3];
            }
            rs1 += __shfl_xor_sync(~0u, rs1, 1); rs1 += __shfl_xor_sync(~0u, rs1, 2);
            rs2 += __shfl_xor_sync(~0u, rs2, 1); rs2 += __shfl_xor_sync(~0u, rs2, 2);
            l1 = l1 * sc1 + rs1;
            l2 = l2 * sc2 + rs2;
#pragma unroll
            for (int i = 0; i < 16; i++) {
                O[i][0] *= sc1; O[i][1] *= sc1; O[i][2] *= sc2; O[i][3] *= sc2;
            }

#pragma unroll
            for (int ks2 = 0; ks2 < 4; ks2++) {
                uint32_t pa_h[4], pa_l[4];
#pragma unroll
                for (int half = 0; half < 2; half++) {
                    const int nt = 2 * ks2 + half;
                    bf16 h0, g0, h1, g1, h2, g2, h3, g3;
                    split_bf16(S[nt][0], h0, g0); split_bf16(S[nt][1], h1, g1);
                    split_bf16(S[nt][2], h2, g2); split_bf16(S[nt][3], h3, g3);
                    pa_h[half ? 2 : 0] = b2u(__nv_bfloat162(h0, h1));
                    pa_h[half ? 3 : 1] = b2u(__nv_bfloat162(h2, h3));
                    pa_l[half ? 2 : 0] = b2u(__nv_bfloat162(g0, g1));
                    pa_l[half ? 3 : 1] = b2u(__nv_bfloat162(g2, g3));
                }
#pragma unroll
                for (int p2 = 0; p2 < 8; p2++) {
                    uint32_t rv[4], rvl[4];
                    const uint32_t a = base + 2 * KPL + (p2 * 16 + brow) * VSTRB + ks2 * 32 + bcol;
                    ldm4(rv, a);
                    ldm4(rvl, a + VPL);
                    uint32_t b0[2] = {rv[0], rv[1]},  b1[2] = {rv[2], rv[3]};
                    uint32_t c0[2] = {rvl[0], rvl[1]}, c1[2] = {rvl[2], rvl[3]};
                    mma16816(O[2*p2],   pa_h, b0); mma16816(O[2*p2],   pa_h, c0); mma16816(O[2*p2],   pa_l, b0);
                    mma16816(O[2*p2+1], pa_h, b1); mma16816(O[2*p2+1], pa_h, c1); mma16816(O[2*p2+1], pa_l, b1);
                }
            }
        }
        __syncthreads();
    }

    const float inv1 = 1.f / l1, inv2 = 1.f / l2;
    const int r1 = qrow1, r2 = qrow1 + 8;
    const int colb = h * HDn + (lane & 3) * 2;
#pragma unroll
    for (int nt2 = 0; nt2 < 16; nt2++) {
        const int col = colb + nt2 * 8;
        bf16 a0, b0, a1, b1;
        split_bf16(O[nt2][0] * inv1, a0, b0);
        split_bf16(O[nt2][1] * inv1, a1, b1);
        *reinterpret_cast<uint32_t*>(ohp + (size_t)r1 * Hn + col) = b2u(__nv_bfloat162(a0, a1));
        *reinterpret_cast<uint32_t*>(olp + (size_t)r1 * Hn + col) = b2u(__nv_bfloat162(b0, b1));
        split_bf16(O[nt2][2] * inv2, a0, b0);
        split_bf16(O[nt2][3] * inv2, a1, b1);
        *reinterpret_cast<uint32_t*>(ohp + (size_t)r2 * Hn + col) = b2u(__nv_bfloat162(a0, a1));
        *reinterpret_cast<uint32_t*>(olp + (size_t)r2 * Hn + col) = b2u(__nv_bfloat162(b0, b1));
    }
}

// ---------------- weight transpose + split: in[K,N] fp32 -> out[N*rmul+roff, K] bf16 hi/lo ----
struct __align__(16) B8 { bf16 v[8]; };

__global__ void __launch_bounds__(256)
convT_kernel(const float* __restrict__ in, bf16* __restrict__ hi, bf16* __restrict__ lo,
             int K, int N, int rmul, int roff)
{
    __shared__ float s[32][129];
    const int n0 = blockIdx.x * 128, k0 = blockIdx.y * 32;
    const int t = threadIdx.x;
    const int r = t >> 5, c4 = (t & 31) * 4;
    float4 v[4];
#pragma unroll
    for (int rr = 0; rr < 4; rr++)
        v[rr] = *reinterpret_cast<const float4*>(in + (size_t)(k0 + r + rr * 8) * N + n0 + c4);
#pragma unroll
    for (int rr = 0; rr < 4; rr++) {
        const int k = r + rr * 8;
        s[k][c4] = v[rr].x; s[k][c4+1] = v[rr].y; s[k][c4+2] = v[rr].z; s[k][c4+3] = v[rr].w;
    }
    __syncthreads();
    const int n = t >> 1, kk0 = (t & 1) * 16;
    B8 hb[2], lb[2];
#pragma unroll
    for (int kk = 0; kk < 16; kk++) {
        bf16 h, l;
        split_bf16(s[kk0 + kk][n], h, l);
        hb[kk >> 3].v[kk & 7] = h;
        lb[kk >> 3].v[kk & 7] = l;
    }
    const size_t o = (size_t)((n0 + n) * rmul + roff) * K + k0 + kk0;
    *reinterpret_cast<B8*>(hi + o)     = hb[0];
    *reinterpret_cast<B8*>(hi + o + 8) = hb[1];
    *reinterpret_cast<B8*>(lo + o)     = lb[0];
    *reinterpret_cast<B8*>(lo + o + 8) = lb[1];
}

// ---------------- pack QKV biases into one 2560-vector ----------------
__global__ void packbias_kernel(const float* __restrict__ bq, const float* __restrict__ bk,
                                const float* __restrict__ bv, float* __restrict__ o)
{
    int i = blockIdx.x * 256 + threadIdx.x;
    if (i < 2048) o[i] = bq[i];
    else if (i < 2304) o[i] = bk[i - 2048];
    else if (i < 2560) o[i] = bv[i - 2304];
}

// ---------------- RMSNorm: MODE 0 -> fp32 out, MODE 1 -> bf16 hi/lo ----------------
template<int MODE>
__global__ void __launch_bounds__(256)
rmsnorm_kernel(const float* __restrict__ x, const float* __restrict__ w,
               float* __restrict__ yf, bf16* __restrict__ yh, bf16* __restrict__ yl)
{
    int s = blockIdx.x;
    const float* row = x + (size_t)s * Hn;
    float4 buf[2];
    float ss = 0.f;
#pragma unroll
    for (int it = 0; it < 2; it++) {
        int j = (it * 256 + threadIdx.x) * 4;
        float4 v = *reinterpret_cast<const float4*>(row + j);
        buf[it] = v;
        ss += v.x * v.x + v.y * v.y + v.z * v.z + v.w * v.w;
    }
    ss = blockSum256(ss);
    float inv = rsqrtf(ss * (1.0f / Hn) + EPSn);
#pragma unroll
    for (int it = 0; it < 2; it++) {
        int j = (it * 256 + threadIdx.x) * 4;
        float4 wv = *reinterpret_cast<const float4*>(w + j);
        float o0 = buf[it].x * inv * wv.x;
        float o1 = buf[it].y * inv * wv.y;
        float o2 = buf[it].z * inv * wv.z;
        float o3 = buf[it].w * inv * wv.w;
        if (MODE == 0) {
            *reinterpret_cast<float4*>(yf + (size_t)s * Hn + j) = make_float4(o0, o1, o2, o3);
        } else {
            bf16 h0,l0,h1,l1,h2,l2,h3,l3;
            split_bf16(o0,h0,l0); split_bf16(o1,h1,l1);
            split_bf16(o2,h2,l2); split_bf16(o3,h3,l3);
            __nv_bfloat162 hh0(h0,h1), hh1(h2,h3), ll0(l0,l1), ll1(l2,l3);
            uint2 uh = make_uint2(b2u(hh0), b2u(hh1));
            uint2 ul = make_uint2(b2u(ll0), b2u(ll1));
            *reinterpret_cast<uint2*>(yh + (size_t)s * Hn + j) = uh;
            *reinterpret_cast<uint2*>(yl + (size_t)s * Hn + j) = ul;
        }
    }
}

// ---------------- RoPE for Q: fp32 (strided in qkv) -> bf16 hi/lo dense [S,2048] ----------------
__global__ void rope_q_kernel(const float* __restrict__ qkv, const int* __restrict__ pos,
                              bf16* __restrict__ qh, bf16* __restrict__ ql)
{
    int s = blockIdx.x, h = blockIdx.y, d = threadIdx.x; // d in [0,64)
    double ang = (double)pos[s] * exp(-(double)d / 64.0 * 13.815510557964274);
    double sd, cd; sincos(ang, &sd, &cd);
    float c = (float)cd, sn = (float)sd;
    size_t ibase = (size_t)s * 2560 + h * HDn;
    size_t obase = ((size_t)s * NHn + h) * HDn;
    float x1 = qkv[ibase + d], x2 = qkv[ibase + d + 64];
    float v1 = x1 * c - x2 * sn;
    float v2 = x2 * c + x1 * sn;
    bf16 hh, ll;
    split_bf16(v1, hh, ll); qh[obase + d] = hh;      ql[obase + d] = ll;
    split_bf16(v2, hh, ll); qh[obase + d + 64] = hh; ql[obase + d + 64] = ll;
}

// ---------------- K/V cache: tiled 32t x 128d; coalesced transposed V via smem ----------------
__global__ void __launch_bounds__(256)
kv_cache_kernel(const float* __restrict__ qkv,
                const float* __restrict__ pastk, const float* __restrict__ pastv,
                const int* __restrict__ pos,
                float* __restrict__ kc, float* __restrict__ vc,
                bf16* __restrict__ kh, bf16* __restrict__ kl,
                bf16* __restrict__ vth, bf16* __restrict__ vtl)
{
    __shared__ float sv[32][129];
    const int t0 = blockIdx.x * 32, kv = blockIdx.y;
    const int tid = threadIdx.x;

#pragma unroll
    for (int i = 0; i < 16; i++) {
        const int idx = i * 256 + tid;          // 0..4095
        const int tt = idx >> 7, d = idx & 127;
        const int t = t0 + tt;
        float kval, vval;
        if (t < Pn) {
            size_t pidx = ((size_t)kv * Pn + t) * HDn + d;
            kval = pastk[pidx];
            vval = pastv[pidx];
        } else {
            int s = t - Pn;
            const float* kr = qkv + (size_t)s * 2560 + 2048 + kv * HDn;
            int dr = d & 63;
            double ang = (double)pos[s] * exp(-(double)dr / 64.0 * 13.815510557964274);
            double sd, cd; sincos(ang, &sd, &cd);
            float c = (float)cd, sn = (float)sd;
            if (d < 64) kval = kr[d] * c - kr[d + 64] * sn;
            else        kval = kr[d] * c + kr[d - 64] * sn;
            vval = qkv[(size_t)s * 2560 + 2304 + kv * HDn + d];
        }
        size_t oidx = ((size_t)kv * Tn + t) * HDn + d;
        kc[oidx] = kval;
        vc[oidx] = vval;
        bf16 h, l;
        split_bf16(kval, h, l);
        kh[oidx] = h; kl[oidx] = l;
        sv[tt][d] = vval;
    }
    __syncthreads();

    const int tt = tid & 31, dw = tid >> 5;
#pragma unroll
    for (int d0 = 0; d0 < 128; d0 += 8) {
        const int d = d0 + dw;
        bf16 h, l;
        split_bf16(sv[tt][d], h, l);
        size_t o = ((size_t)kv * HDn + d) * Tn + t0 + tt;
        vth[o] = h; vtl[o] = l;
    }
}

// ---------------- host-side launch helpers ----------------
static void mmagemm(const bf16* Ah, const bf16* Al, const bf16* Bh, const bf16* Bl,
                    const float* bias, const float* Res, float* Cf,
                    int M, int N, int K, int lda, int ldb, int ldc)
{
    dim3 grid(N / 128, M / 128, 1);
    mma_gemm<0><<<grid, 256, NSTAGE * STAGEB>>>(Ah, Al, Bh, Bl, bias, Res, Cf,
                                                nullptr, nullptr, K, lda, ldb, ldc);
}
static void mmagemm_gu(const bf16* Ah, const bf16* Al, const bf16* Bh, const bf16* Bl,
                       bf16* Chi, bf16* Clo, int M, int N, int K, int lda, int ldb, int ldc)
{
    dim3 grid(N / 128, M / 128, 1);
    mma_gemm<1><<<grid, 256, NSTAGE * STAGEB>>>(Ah, Al, Bh, Bl, nullptr, nullptr, nullptr,
                                                Chi, Clo, K, lda, ldb, ldc);
}

extern "C" void kernel_launch(void* const* d_in, const int* in_sizes, int n_in,
                              void* d_out, int out_size)
{
    (void)in_sizes; (void)n_in; (void)out_size;
    const float* embeds = (const float*)d_in[0];
    const int*   pos    = (const int*)  d_in[1];
    const float* past_k = (const float*)d_in[2];
    const float* past_v = (const float*)d_in[3];
    const float* ln1    = (const float*)d_in[4];
    const float* wq     = (const float*)d_in[5];
    const float* bq     = (const float*)d_in[6];
    const float* wk     = (const float*)d_in[7];
    const float* bk     = (const float*)d_in[8];
    const float* wv     = (const float*)d_in[9];
    const float* bv     = (const float*)d_in[10];
    const float* wo     = (const float*)d_in[11];
    const float* ln2    = (const float*)d_in[12];
    const float* wg     = (const float*)d_in[13];
    const float* wu     = (const float*)d_in[14];
    const float* wd     = (const float*)d_in[15];
    const float* normw  = (const float*)d_in[16];
    float* out = (float*)d_out;

    cudaFuncSetAttribute(mma_gemm<0>, cudaFuncAttributeMaxDynamicSharedMemorySize, NSTAGE * STAGEB);
    cudaFuncSetAttribute(mma_gemm<1>, cudaFuncAttributeMaxDynamicSharedMemorySize, NSTAGE * STAGEB);
    cudaFuncSetAttribute(flash_kernel, cudaFuncAttributeMaxDynamicSharedMemorySize, FSMEM);

    float *hid, *qkv, *bqkv;
    cudaGetSymbolAddress((void**)&hid,  g_hid);
    cudaGetSymbolAddress((void**)&qkv,  g_qkv);
    cudaGetSymbolAddress((void**)&bqkv, g_bqkv);
    bf16 *hnh,*hnl,*qh,*ql,*kh,*kl,*vth,*vtl,*ath,*atl,*gh,*gl,*wh,*wl;
    cudaGetSymbolAddress((void**)&hnh, g_hn_hi); cudaGetSymbolAddress((void**)&hnl, g_hn_lo);
    cudaGetSymbolAddress((void**)&qh,  g_q_hi);  cudaGetSymbolAddress((void**)&ql,  g_q_lo);
    cudaGetSymbolAddress((void**)&kh,  g_k_hi);  cudaGetSymbolAddress((void**)&kl,  g_k_lo);
    cudaGetSymbolAddress((void**)&vth, g_vt_hi); cudaGetSymbolAddress((void**)&vtl, g_vt_lo);
    cudaGetSymbolAddress((void**)&ath, g_at_hi); cudaGetSymbolAddress((void**)&atl, g_at_lo);
    cudaGetSymbolAddress((void**)&gh,  g_g_hi);  cudaGetSymbolAddress((void**)&gl,  g_g_lo);
    cudaGetSymbolAddress((void**)&wh,  g_w_hi);  cudaGetSymbolAddress((void**)&wl,  g_w_lo);

    // per-layer offsets into transposed weight store
    // [OQ: qkv 2560 rows][OO: wo 2048 rows][OG: gate/up interleaved 11264 rows][OD: wd 2048 rows]
    const long long OQ = 0, OO = 5242880, OG = 9437184, OD = 32505856;
    const long long OK_ = 4194304, OV = 4718592;

    // ---- second stream for weight-conversion overlap (leaked; few calls total) ----
    cudaStream_t s2;
    cudaStreamCreateWithFlags(&s2, cudaStreamNonBlocking);
    cudaEvent_t evFork, evJoin;
    cudaEventCreateWithFlags(&evFork, cudaEventDisableTiming);
    cudaEventCreateWithFlags(&evJoin, cudaEventDisableTiming);

    dim3 cb(256);
    // fork: s2 depends only on capture start
    cudaEventRecord(evFork, 0);
    cudaStreamWaitEvent(s2, evFork, 0);

    // critical-path convT (layer 0 QKV weights) on stream 0
    {
        long long base = 0;
        convT_kernel<<<dim3(2048/128, 2048/32), cb>>>(wq, wh + base + OQ,  wl + base + OQ,  Hn, 2048, 1, 0);
        convT_kernel<<<dim3(256/128,  2048/32), cb>>>(wk, wh + base + OK_, wl + base + OK_, Hn, 256, 1, 0);
        convT_kernel<<<dim3(256/128,  2048/32), cb>>>(wv, wh + base + OV,  wl + base + OV,  Hn, 256, 1, 0);
    }
    // all remaining convT on s2 (overlaps layer-0 front)
    {
        long long b0 = 0;
        convT_kernel<<<dim3(2048/128, 2048/32), cb, 0, s2>>>(wo, wh + b0 + OO, wl + b0 + OO, Hn, 2048, 1, 0);
        convT_kernel<<<dim3(5632/128, 2048/32), cb, 0, s2>>>(wg, wh + b0 + OG, wl + b0 + OG, Hn, FFn, 2, 0);
        convT_kernel<<<dim3(5632/128, 2048/32), cb, 0, s2>>>(wu, wh + b0 + OG, wl + b0 + OG, Hn, FFn, 2, 1);
        convT_kernel<<<dim3(2048/128, 5632/32), cb, 0, s2>>>(wd, wh + b0 + OD, wl + b0 + OD, FFn, 2048, 1, 0);
        long long b1 = WL;
        convT_kernel<<<dim3(2048/128, 2048/32), cb, 0, s2>>>(wq + (size_t)Hn*2048, wh + b1 + OQ,  wl + b1 + OQ,  Hn, 2048, 1, 0);
        convT_kernel<<<dim3(256/128,  2048/32), cb, 0, s2>>>(wk + (size_t)Hn*256,  wh + b1 + OK_, wl + b1 + OK_, Hn, 256, 1, 0);
        convT_kernel<<<dim3(256/128,  2048/32), cb, 0, s2>>>(wv + (size_t)Hn*256,  wh + b1 + OV,  wl + b1 + OV,  Hn, 256, 1, 0);
        convT_kernel<<<dim3(2048/128, 2048/32), cb, 0, s2>>>(wo + (size_t)Hn*Hn,   wh + b1 + OO,  wl + b1 + OO,  Hn, 2048, 1, 0);
        convT_kernel<<<dim3(5632/128, 2048/32), cb, 0, s2>>>(wg + (size_t)Hn*FFn,  wh + b1 + OG,  wl + b1 + OG,  Hn, FFn, 2, 0);
        convT_kernel<<<dim3(5632/128, 2048/32), cb, 0, s2>>>(wu + (size_t)Hn*FFn,  wh + b1 + OG,  wl + b1 + OG,  Hn, FFn, 2, 1);
        convT_kernel<<<dim3(2048/128, 5632/32), cb, 0, s2>>>(wd + (size_t)FFn*Hn,  wh + b1 + OD,  wl + b1 + OD,  FFn, 2048, 1, 0);
        cudaEventRecord(evJoin, s2);
    }

    cudaMemcpyAsync(hid, embeds, sizeof(float) * Sn * Hn, cudaMemcpyDeviceToDevice);

    bool joined = false;
    for (int l = 0; l < Ln; l++) {
        long long base = (long long)l * WL;
        float* kc = out + (size_t)Sn * Hn + (size_t)l * 2 * NKVn * Tn * HDn;
        float* vc = kc + (size_t)NKVn * Tn * HDn;

        // pre-attention norm -> bf16 hi/lo
        rmsnorm_kernel<1><<<Sn, 256>>>(hid, ln1 + (size_t)l * Hn, nullptr, hnh, hnl);

        // fused QKV projection (N=2560) -> fp32 qkv buffer
        packbias_kernel<<<10, 256>>>(bq + (size_t)l*2048, bk + (size_t)l*256, bv + (size_t)l*256, bqkv);
        mmagemm(hnh, hnl, wh + base + OQ, wl + base + OQ, bqkv, nullptr,
                qkv, Sn, 2560, Hn, Hn, Hn, 2560);

        // RoPE Q -> bf16 hi/lo; KV cache (fp32 to d_out + bf16 hi/lo, V transposed)
        rope_q_kernel<<<dim3(Sn, NHn), 64>>>(qkv, pos, qh, ql);
        kv_cache_kernel<<<dim3(Tn / 32, NKVn), 256>>>(
            qkv,
            past_k + (size_t)l * NKVn * Pn * HDn,
            past_v + (size_t)l * NKVn * Pn * HDn,
            pos, kc, vc, kh, kl, vth, vtl);

        // fused attention (paired causal blocks): QK^T -> online softmax -> PV
        flash_kernel<<<dim3(8, NHn), 256, FSMEM>>>(qh, ql, kh, kl, vth, vtl, ath, atl);

        // join s2 before first use of non-QKV weights
        if (!joined) { cudaStreamWaitEvent(0, evJoin, 0); joined = true; }

        // output projection + residual (fp32)
        mmagemm(ath, atl, wh + base + OO, wl + base + OO, nullptr, hid,
                hid, Sn, Hn, Hn, Hn, Hn, Hn);

        // MLP: gate|up interleaved GEMM with fused SiLU epilogue -> bf16 hi/lo, then down
        rmsnorm_kernel<1><<<Sn, 256>>>(hid, ln2 + (size_t)l * Hn, nullptr, hnh, hnl);
        mmagemm_gu(hnh, hnl, wh + base + OG, wl + base + OG, gh, gl,
                   Sn, 2*FFn, Hn, Hn, Hn, FFn);
        mmagemm(gh, gl, wh + base + OD, wl + base + OD, nullptr, hid,
                hid, Sn, Hn, FFn, FFn, FFn, Hn);
    }

    // final norm -> fp32 hidden output
    rmsnorm_kernel<0><<<Sn, 256>>>(hid, normw, out, nullptr, nullptr);
}